// round 11
// baseline (speedup 1.0000x reference)
#include <cuda_runtime.h>
#include <cuda_bf16.h>
#include <cstdint>
#include <math.h>

// Problem constants
#define BB 2
#define TT 2048
#define CC 2048
#define HH 32
#define HKV 8
#define DD 64
#define MROWS (BB*TT)          // 4096
#define NQKV 3072              // H*D + 2*HKV*D

// Scratch (device globals: allocation-free per harness rules)
__device__ float g_qkv[MROWS * NQKV];          // [m][3072]  q|k|v
__device__ float g_q[BB * HH * TT * DD];       // [b][h][t][d]  (RoPE'd, tf32-rounded)
__device__ float g_k[BB * HKV * TT * DD];      // [b][hk][t][d] (RoPE'd, tf32-rounded)
__device__ float g_y[MROWS * CC];              // attention out (tf32-rounded)
__device__ float g_ct[TT * 32];                // cos table
__device__ float g_st[TT * 32];                // sin table
// tf32-pre-rounded GEMM operands
__device__ float g_xt[MROWS * CC];             // x rounded
__device__ float g_wt[NQKV * CC];              // [Wq;Wk;Wv] rounded
__device__ float g_wct[CC * CC];               // Wc rounded

// ---------------------------------------------------------------------------
// helpers
// ---------------------------------------------------------------------------
__device__ __forceinline__ uint32_t f2tf(float f) {
    uint32_t r;
    asm("cvt.rna.tf32.f32 %0, %1;" : "=r"(r) : "f"(f));
    return r;
}

__device__ __forceinline__ void mma_tf32(float* c,
                                         uint32_t a0, uint32_t a1, uint32_t a2, uint32_t a3,
                                         uint32_t b0, uint32_t b1) {
    asm volatile(
        "mma.sync.aligned.m16n8k8.row.col.f32.tf32.tf32.f32 "
        "{%0,%1,%2,%3}, {%4,%5,%6,%7}, {%8,%9}, {%0,%1,%2,%3};"
        : "+f"(c[0]), "+f"(c[1]), "+f"(c[2]), "+f"(c[3])
        : "r"(a0), "r"(a1), "r"(a2), "r"(a3), "r"(b0), "r"(b1));
}

// ---------------------------------------------------------------------------
// elementwise tf32 rounding
// ---------------------------------------------------------------------------
__global__ void round_tf(const float* __restrict__ s, float* __restrict__ d, int n4)
{
    int i = blockIdx.x * blockDim.x + threadIdx.x;
    if (i >= n4) return;
    float4 v = ((const float4*)s)[i];
    v.x = __uint_as_float(f2tf(v.x));
    v.y = __uint_as_float(f2tf(v.y));
    v.z = __uint_as_float(f2tf(v.z));
    v.w = __uint_as_float(f2tf(v.w));
    ((float4*)d)[i] = v;
}

// round the V region of qkv (cols 2560..3071) in place
__global__ void round_v(float* __restrict__ qkv)
{
    int idx = blockIdx.x * blockDim.x + threadIdx.x;   // 4096*128
    int m = idx >> 7, c4 = idx & 127;
    float4* p = (float4*)(qkv + (size_t)m * NQKV + 2560) + c4;
    float4 v = *p;
    v.x = __uint_as_float(f2tf(v.x));
    v.y = __uint_as_float(f2tf(v.y));
    v.z = __uint_as_float(f2tf(v.z));
    v.w = __uint_as_float(f2tf(v.w));
    *p = v;
}

// ---------------------------------------------------------------------------
// tf32 tensor-core GEMM: C[m][n] = sum_k A[m][k]*B[n][k]; operands pre-rounded.
// 128x128x16 tile, 256 threads (8 warps 4x2, warp tile 32x64).
// Register prefetch + double-buffered smem -> one barrier per K-tile.
// ---------------------------------------------------------------------------
#define SROW 20
#define HALF (128 * SROW)
#define GEMM_SMEM (4 * HALF * 4)    // 2 buffers x (A+B) x 128*SROW floats = 81920 B

__global__ __launch_bounds__(256)
void gemm_tf32(const float* __restrict__ A, const float* __restrict__ B,
               float* __restrict__ C, int ldc)
{
    extern __shared__ uint32_t gsm[];
    // layout: [buf0: As | Bs][buf1: As | Bs]
    const int tid = threadIdx.x;
    const int lane = tid & 31, w = tid >> 5;
    const int wm = w >> 1, wn = w & 1;
    const int g = lane >> 2, tg = lane & 3;
    const int bm = blockIdx.y * 128, bn = blockIdx.x * 128;
    const int lr = tid >> 1, lc = (tid & 1) * 8;

    const float* Ap = A + (size_t)(bm + lr) * 2048 + lc;
    const float* Bp = B + (size_t)(bn + lr) * 2048 + lc;

    float acc[16][4];
#pragma unroll
    for (int i = 0; i < 16; i++)
#pragma unroll
        for (int j = 0; j < 4; j++) acc[i][j] = 0.f;

    const int nt = 128;   // K / 16

    uint4 ra0 = *(const uint4*)(Ap);
    uint4 ra1 = *(const uint4*)(Ap + 4);
    uint4 rb0 = *(const uint4*)(Bp);
    uint4 rb1 = *(const uint4*)(Bp + 4);

    uint32_t* const wp = gsm + lr * SROW + lc;

    // store tile 0 into buffer 0
    *(uint4*)(wp)              = ra0;
    *(uint4*)(wp + 4)          = ra1;
    *(uint4*)(wp + HALF)       = rb0;
    *(uint4*)(wp + HALF + 4)   = rb1;
    __syncthreads();

    for (int kt = 0; kt < nt; kt++) {
        if (kt + 1 < nt) {
            const float* An = Ap + (size_t)(kt + 1) * 16;
            const float* Bn = Bp + (size_t)(kt + 1) * 16;
            ra0 = *(const uint4*)(An);
            ra1 = *(const uint4*)(An + 4);
            rb0 = *(const uint4*)(Bn);
            rb1 = *(const uint4*)(Bn + 4);
        }

        const uint32_t* as = gsm + (kt & 1) * 2 * HALF;
        const uint32_t* bs = as + HALF;
#pragma unroll
        for (int kk = 0; kk < 16; kk += 8) {
            uint32_t af[2][4], bf[8][2];
#pragma unroll
            for (int mi = 0; mi < 2; mi++) {
                int r = wm * 32 + mi * 16 + g;
                af[mi][0] = as[r * SROW + kk + tg];
                af[mi][1] = as[(r + 8) * SROW + kk + tg];
                af[mi][2] = as[r * SROW + kk + tg + 4];
                af[mi][3] = as[(r + 8) * SROW + kk + tg + 4];
            }
#pragma unroll
            for (int ni = 0; ni < 8; ni++) {
                int n = wn * 64 + ni * 8 + g;
                bf[ni][0] = bs[n * SROW + kk + tg];
                bf[ni][1] = bs[n * SROW + kk + tg + 4];
            }
#pragma unroll
            for (int mi = 0; mi < 2; mi++)
#pragma unroll
                for (int ni = 0; ni < 8; ni++)
                    mma_tf32(acc[mi * 8 + ni],
                             af[mi][0], af[mi][1], af[mi][2], af[mi][3],
                             bf[ni][0], bf[ni][1]);
        }

        if (kt + 1 < nt) {
            uint32_t* wd = gsm + ((kt + 1) & 1) * 2 * HALF + lr * SROW + lc;
            *(uint4*)(wd)            = ra0;
            *(uint4*)(wd + 4)        = ra1;
            *(uint4*)(wd + HALF)     = rb0;
            *(uint4*)(wd + HALF + 4) = rb1;
        }
        __syncthreads();
    }

#pragma unroll
    for (int mi = 0; mi < 2; mi++) {
        int row = bm + wm * 32 + mi * 16 + g;
#pragma unroll
        for (int ni = 0; ni < 8; ni++) {
            int col = bn + wn * 64 + ni * 8 + tg * 2;
            const float* a = acc[mi * 8 + ni];
            *(float2*)&C[(size_t)row * ldc + col]       = make_float2(a[0], a[1]);
            *(float2*)&C[(size_t)(row + 8) * ldc + col] = make_float2(a[2], a[3]);
        }
    }
}

// ---------------------------------------------------------------------------
// RoPE cos/sin table (double precision)
// ---------------------------------------------------------------------------
__global__ void rope_tab(const int* __restrict__ pos,
                         float* __restrict__ ct, float* __restrict__ st)
{
    int idx = blockIdx.x * blockDim.x + threadIdx.x;
    if (idx >= TT * 32) return;
    int t = idx >> 5, j = idx & 31;
    double ang = (double)pos[t] * pow(10000.0, -(double)j / 32.0);
    double s, c;
    sincos(ang, &s, &c);
    ct[idx] = (float)c;
    st[idx] = (float)s;
}

// ---------------------------------------------------------------------------
// RoPE + reshape; stores tf32-rounded so flash loads raw bits.
// ---------------------------------------------------------------------------
__global__ void rope_reshape(const float* __restrict__ qkv,
                             const float* __restrict__ ct, const float* __restrict__ st,
                             float* __restrict__ Qr, float* __restrict__ Kr)
{
    const int PPT = (HH + HKV) * 32;
    int idx = blockIdx.x * blockDim.x + threadIdx.x;
    if (idx >= BB * TT * PPT) return;
    int m = idx / PPT;
    int r = idx - m * PPT;
    int head = r >> 5, dp = r & 31;
    int b = m / TT, t = m - b * TT;

    const float* row = qkv + (size_t)m * NQKV;
    float x0, x1;
    float* dst;
    if (head < HH) {
        x0 = row[head * 64 + dp];
        x1 = row[head * 64 + dp + 32];
        dst = Qr + ((size_t)(b * HH + head) * TT + t) * 64;
    } else {
        int hk = head - HH;
        x0 = row[2048 + hk * 64 + dp];
        x1 = row[2048 + hk * 64 + dp + 32];
        dst = Kr + ((size_t)(b * HKV + hk) * TT + t) * 64;
    }
    int j = dp >> 1;
    float c1 = ct[t * 32 + j],      s1 = st[t * 32 + j];
    float c2 = ct[t * 32 + j + 16], s2 = st[t * 32 + j + 16];
    dst[dp]      = __uint_as_float(f2tf(x0 * c1 - x1 * s1));
    dst[dp + 32] = __uint_as_float(f2tf(x1 * c2 + x0 * s2));
}

// ---------------------------------------------------------------------------
// Tensor-core flash attention (tf32 mma, fp32 softmax in registers).
// Q/K/V pre-rounded to tf32 -> loads are raw bit copies.
// ---------------------------------------------------------------------------
#define FS 68
#define FLASH_SMEM (384 * FS * 4)

__global__ __launch_bounds__(256)
void flash_attn_tc(const float* __restrict__ Q, const float* __restrict__ K,
                   const float* __restrict__ Vg, float* __restrict__ Y)
{
    extern __shared__ uint32_t smu[];
    uint32_t* Qs = smu;                 // [128][FS]
    uint32_t* Ks = Qs + 128 * FS;       // [64][FS]
    uint32_t* Vs = Ks + 64 * FS;        // [64][FS]
    uint32_t* Ps = Vs + 64 * FS;        // [128][FS], per-warp-private rows

    const int tid = threadIdx.x;
    const int lane = tid & 31, w = tid >> 5;
    const int g = lane >> 2, tg = lane & 3;
    const int qt = (gridDim.x - 1) - blockIdx.x;   // heavy blocks first
    const int h = blockIdx.y, b = blockIdx.z, hk = h >> 2;
    const int qbase = qt * 128;
    const float scale = 0.125f;

    {
        int r = tid >> 1, c0 = (tid & 1) * 32;
        const uint4* src = (const uint4*)(Q + (((size_t)(b * HH + h) * TT) + qbase + r) * 64 + c0);
        uint4* dst = (uint4*)(Qs + r * FS + c0);
#pragma unroll
        for (int i = 0; i < 8; i++) dst[i] = src[i];
    }

    float Oc[8][4];
#pragma unroll
    for (int i = 0; i < 8; i++)
#pragma unroll
        for (int j = 0; j < 4; j++) Oc[i][j] = 0.f;

    float mrun0 = -1e30f, mrun1 = -1e30f, lrun0 = 0.f, lrun1 = 0.f;
    const int row0 = qbase + w * 16 + g;
    const int row1 = row0 + 8;
    const int slab = w * 16;

    const int nkv = 2 * qt + 2;
    for (int jt = 0; jt < nkv; jt++) {
        const int kbase = jt * 64;
        __syncthreads();
        {
            int r = tid >> 2, c0 = (tid & 3) * 16;
            const uint4* ks = (const uint4*)(K + (((size_t)(b * HKV + hk) * TT) + kbase + r) * 64 + c0);
            const uint4* vs = (const uint4*)(Vg + ((size_t)(b * TT + kbase + r)) * NQKV + hk * 64 + c0);
            uint4* kd = (uint4*)(Ks + r * FS + c0);
            uint4* vd = (uint4*)(Vs + r * FS + c0);
#pragma unroll
            for (int i = 0; i < 4; i++) {
                kd[i] = ks[i];
                vd[i] = vs[i];
            }
        }
        __syncthreads();

        float Sc[8][4];
#pragma unroll
        for (int i = 0; i < 8; i++)
#pragma unroll
            for (int j = 0; j < 4; j++) Sc[i][j] = 0.f;
#pragma unroll
        for (int kk = 0; kk < 64; kk += 8) {
            uint32_t a0 = Qs[(slab + g) * FS + kk + tg];
            uint32_t a1 = Qs[(slab + g + 8) * FS + kk + tg];
            uint32_t a2 = Qs[(slab + g) * FS + kk + tg + 4];
            uint32_t a3 = Qs[(slab + g + 8) * FS + kk + tg + 4];
#pragma unroll
            for (int ni = 0; ni < 8; ni++) {
                uint32_t b0 = Ks[(ni * 8 + g) * FS + kk + tg];
                uint32_t b1 = Ks[(ni * 8 + g) * FS + kk + tg + 4];
                mma_tf32(Sc[ni], a0, a1, a2, a3, b0, b1);
            }
        }

        const bool needmask = (kbase + 63) > (qbase + slab);
        float mx0 = -1e30f, mx1 = -1e30f;
#pragma unroll
        for (int ni = 0; ni < 8; ni++) {
            int c = kbase + ni * 8 + 2 * tg;
            float s0 = Sc[ni][0] * scale, s1 = Sc[ni][1] * scale;
            float s2 = Sc[ni][2] * scale, s3 = Sc[ni][3] * scale;
            if (needmask) {
                if (c     > row0) s0 = -1e30f;
                if (c + 1 > row0) s1 = -1e30f;
                if (c     > row1) s2 = -1e30f;
                if (c + 1 > row1) s3 = -1e30f;
            }
            Sc[ni][0] = s0; Sc[ni][1] = s1; Sc[ni][2] = s2; Sc[ni][3] = s3;
            mx0 = fmaxf(mx0, fmaxf(s0, s1));
            mx1 = fmaxf(mx1, fmaxf(s2, s3));
        }
        mx0 = fmaxf(mx0, __shfl_xor_sync(0xffffffffu, mx0, 1));
        mx0 = fmaxf(mx0, __shfl_xor_sync(0xffffffffu, mx0, 2));
        mx1 = fmaxf(mx1, __shfl_xor_sync(0xffffffffu, mx1, 1));
        mx1 = fmaxf(mx1, __shfl_xor_sync(0xffffffffu, mx1, 2));

        float nm0 = fmaxf(mrun0, mx0), nm1 = fmaxf(mrun1, mx1);
        float ps0 = 0.f, ps1 = 0.f;
#pragma unroll
        for (int ni = 0; ni < 8; ni++) {
            float p0 = __expf(Sc[ni][0] - nm0);
            float p1 = __expf(Sc[ni][1] - nm0);
            float p2 = __expf(Sc[ni][2] - nm1);
            float p3 = __expf(Sc[ni][3] - nm1);
            ps0 += p0 + p1; ps1 += p2 + p3;
            Ps[(slab + g) * FS + ni * 8 + 2 * tg]         = f2tf(p0);
            Ps[(slab + g) * FS + ni * 8 + 2 * tg + 1]     = f2tf(p1);
            Ps[(slab + g + 8) * FS + ni * 8 + 2 * tg]     = f2tf(p2);
            Ps[(slab + g + 8) * FS + ni * 8 + 2 * tg + 1] = f2tf(p3);
        }
        ps0 += __shfl_xor_sync(0xffffffffu, ps0, 1);
        ps0 += __shfl_xor_sync(0xffffffffu, ps0, 2);
        ps1 += __shfl_xor_sync(0xffffffffu, ps1, 1);
        ps1 += __shfl_xor_sync(0xffffffffu, ps1, 2);

        float rf0 = __expf(mrun0 - nm0), rf1 = __expf(mrun1 - nm1);
        lrun0 = lrun0 * rf0 + ps0;  lrun1 = lrun1 * rf1 + ps1;
        mrun0 = nm0;  mrun1 = nm1;
#pragma unroll
        for (int ni = 0; ni < 8; ni++) {
            Oc[ni][0] *= rf0; Oc[ni][1] *= rf0;
            Oc[ni][2] *= rf1; Oc[ni][3] *= rf1;
        }
        __syncwarp();

#pragma unroll
        for (int kk = 0; kk < 64; kk += 8) {
            uint32_t a0 = Ps[(slab + g) * FS + kk + tg];
            uint32_t a1 = Ps[(slab + g + 8) * FS + kk + tg];
            uint32_t a2 = Ps[(slab + g) * FS + kk + tg + 4];
            uint32_t a3 = Ps[(slab + g + 8) * FS + kk + tg + 4];
#pragma unroll
            for (int ni = 0; ni < 8; ni++) {
                uint32_t b0 = Vs[(kk + tg) * FS + ni * 8 + g];
                uint32_t b1 = Vs[(kk + tg + 4) * FS + ni * 8 + g];
                mma_tf32(Oc[ni], a0, a1, a2, a3, b0, b1);
            }
        }
    }

    // Normalize + tf32-round + write y (feeds proj GEMM raw)
    float inv0 = 1.0f / lrun0, inv1 = 1.0f / lrun1;
#pragma unroll
    for (int ni = 0; ni < 8; ni++) {
        int col = h * 64 + ni * 8 + 2 * tg;
        *(float2*)&Y[((size_t)(b * TT) + row0) * CC + col] =
            make_float2(__uint_as_float(f2tf(Oc[ni][0] * inv0)),
                        __uint_as_float(f2tf(Oc[ni][1] * inv0)));
        *(float2*)&Y[((size_t)(b * TT) + row1) * CC + col] =
            make_float2(__uint_as_float(f2tf(Oc[ni][2] * inv1)),
                        __uint_as_float(f2tf(Oc[ni][3] * inv1)));
    }
}

// ---------------------------------------------------------------------------
extern "C" void kernel_launch(void* const* d_in, const int* in_sizes, int n_in,
                              void* d_out, int out_size)
{
    const float* x  = (const float*)d_in[0];
    const float* Wq = (const float*)d_in[1];
    const float* Wk = (const float*)d_in[2];
    const float* Wv = (const float*)d_in[3];
    const float* Wc = (const float*)d_in[4];
    const int* pos  = (const int*)d_in[5];
    float* out = (float*)d_out;

    float *qkv, *q, *k, *y, *ct, *st, *xt, *wt, *wct;
    cudaGetSymbolAddress((void**)&qkv, g_qkv);
    cudaGetSymbolAddress((void**)&q,   g_q);
    cudaGetSymbolAddress((void**)&k,   g_k);
    cudaGetSymbolAddress((void**)&y,   g_y);
    cudaGetSymbolAddress((void**)&ct,  g_ct);
    cudaGetSymbolAddress((void**)&st,  g_st);
    cudaGetSymbolAddress((void**)&xt,  g_xt);
    cudaGetSymbolAddress((void**)&wt,  g_wt);
    cudaGetSymbolAddress((void**)&wct, g_wct);

    cudaFuncSetAttribute(gemm_tf32, cudaFuncAttributeMaxDynamicSharedMemorySize, GEMM_SMEM);
    cudaFuncSetAttribute(flash_attn_tc, cudaFuncAttributeMaxDynamicSharedMemorySize, FLASH_SMEM);

    // Pre-round operands to tf32
    round_tf<<<(MROWS * CC / 4) / 256, 256>>>(x, xt, MROWS * CC / 4);
    round_tf<<<(2048 * 2048 / 4) / 256, 256>>>(Wq, wt, 2048 * 2048 / 4);
    round_tf<<<(512 * 2048 / 4) / 256, 256>>>(Wk, wt + 2048 * 2048, 512 * 2048 / 4);
    round_tf<<<(512 * 2048 / 4) / 256, 256>>>(Wv, wt + 2560 * 2048, 512 * 2048 / 4);
    round_tf<<<(2048 * 2048 / 4) / 256, 256>>>(Wc, wct, 2048 * 2048 / 4);

    // QKV projection (M=4096, N=3072 packed)
    gemm_tf32<<<dim3(24, 32), 256, GEMM_SMEM>>>(xt, wt, qkv, NQKV);

    // RoPE
    rope_tab<<<(TT * 32 + 255) / 256, 256>>>(pos, ct, st);
    rope_reshape<<<(BB * TT * (HH + HKV) * 32 + 255) / 256, 256>>>(qkv, ct, st, q, k);
    round_v<<<(MROWS * 128) / 256, 256>>>(qkv);

    // Flash attention (tf32 mma.sync)
    flash_attn_tc<<<dim3(TT / 128, HH, BB), 256, FLASH_SMEM>>>(q, k, qkv + 2560, y);

    // Output projection
    gemm_tf32<<<dim3(16, 32), 256, GEMM_SMEM>>>(y, wct, out, CC);
}

// round 12
// speedup vs baseline: 1.0512x; 1.0512x over previous
#include <cuda_runtime.h>
#include <cuda_bf16.h>
#include <cstdint>
#include <math.h>

// Problem constants
#define BB 2
#define TT 2048
#define CC 2048
#define HH 32
#define HKV 8
#define DD 64
#define MROWS (BB*TT)          // 4096
#define NQKV 3072              // H*D + 2*HKV*D

// Scratch (device globals: allocation-free per harness rules)
__device__ float g_qkv[MROWS * NQKV];          // [m][3072]  q|k|v
__device__ float g_q[BB * HH * TT * DD];       // [b][h][t][d]  (RoPE'd, tf32-rounded)
__device__ float g_k[BB * HKV * TT * DD];      // [b][hk][t][d] (RoPE'd, tf32-rounded)
__device__ float g_y[MROWS * CC];              // attention out (tf32-rounded)
__device__ float g_ct[TT * 32];                // cos table
__device__ float g_st[TT * 32];                // sin table
// tf32-pre-rounded GEMM operands
__device__ float g_xt[MROWS * CC];             // x rounded
__device__ float g_wt[NQKV * CC];              // [Wq;Wk;Wv] rounded
__device__ float g_wct[CC * CC];               // Wc rounded

// ---------------------------------------------------------------------------
// helpers
// ---------------------------------------------------------------------------
__device__ __forceinline__ uint32_t f2tf(float f) {
    uint32_t r;
    asm("cvt.rna.tf32.f32 %0, %1;" : "=r"(r) : "f"(f));
    return r;
}

__device__ __forceinline__ void mma_tf32(float* c,
                                         uint32_t a0, uint32_t a1, uint32_t a2, uint32_t a3,
                                         uint32_t b0, uint32_t b1) {
    asm volatile(
        "mma.sync.aligned.m16n8k8.row.col.f32.tf32.tf32.f32 "
        "{%0,%1,%2,%3}, {%4,%5,%6,%7}, {%8,%9}, {%0,%1,%2,%3};"
        : "+f"(c[0]), "+f"(c[1]), "+f"(c[2]), "+f"(c[3])
        : "r"(a0), "r"(a1), "r"(a2), "r"(a3), "r"(b0), "r"(b1));
}

// ---------------------------------------------------------------------------
// elementwise tf32 rounding
// ---------------------------------------------------------------------------
__global__ void round_tf(const float* __restrict__ s, float* __restrict__ d, int n4)
{
    int i = blockIdx.x * blockDim.x + threadIdx.x;
    if (i >= n4) return;
    float4 v = ((const float4*)s)[i];
    v.x = __uint_as_float(f2tf(v.x));
    v.y = __uint_as_float(f2tf(v.y));
    v.z = __uint_as_float(f2tf(v.z));
    v.w = __uint_as_float(f2tf(v.w));
    ((float4*)d)[i] = v;
}

// round the V region of qkv (cols 2560..3071) in place
__global__ void round_v(float* __restrict__ qkv)
{
    int idx = blockIdx.x * blockDim.x + threadIdx.x;   // 4096*128
    int m = idx >> 7, c4 = idx & 127;
    float4* p = (float4*)(qkv + (size_t)m * NQKV + 2560) + c4;
    float4 v = *p;
    v.x = __uint_as_float(f2tf(v.x));
    v.y = __uint_as_float(f2tf(v.y));
    v.z = __uint_as_float(f2tf(v.z));
    v.w = __uint_as_float(f2tf(v.w));
    *p = v;
}

// ---------------------------------------------------------------------------
// tf32 tensor-core GEMM: C[m][n] = sum_k A[m][k]*B[n][k]; operands pre-rounded.
// 128x128x16 tile, 256 threads (8 warps 4x2, warp tile 32x64).
// R6 ordering (store -> sync -> prefetch LDG -> mma) with double-buffered smem
// so only ONE barrier per K-tile; LDG->STS distance = mma block + barrier.
// ---------------------------------------------------------------------------
#define SROW 20
#define HALF (128 * SROW)
#define GEMM_SMEM (4 * HALF * 4)    // 2 buffers x (A+B) = 81920 B

__global__ __launch_bounds__(256)
void gemm_tf32(const float* __restrict__ A, const float* __restrict__ B,
               float* __restrict__ C, int ldc)
{
    extern __shared__ uint32_t gsm[];
    const int tid = threadIdx.x;
    const int lane = tid & 31, w = tid >> 5;
    const int wm = w >> 1, wn = w & 1;
    const int g = lane >> 2, tg = lane & 3;
    const int bm = blockIdx.y * 128, bn = blockIdx.x * 128;
    const int lr = tid >> 1, lc = (tid & 1) * 8;

    const float* Ap = A + (size_t)(bm + lr) * 2048 + lc;
    const float* Bp = B + (size_t)(bn + lr) * 2048 + lc;

    float acc[16][4];
#pragma unroll
    for (int i = 0; i < 16; i++)
#pragma unroll
        for (int j = 0; j < 4; j++) acc[i][j] = 0.f;

    const int nt = 128;   // K / 16

    // prologue: tile 0 in registers
    uint4 ra0 = *(const uint4*)(Ap);
    uint4 ra1 = *(const uint4*)(Ap + 4);
    uint4 rb0 = *(const uint4*)(Bp);
    uint4 rb1 = *(const uint4*)(Bp + 4);

    for (int kt = 0; kt < nt; kt++) {
        // store tile kt (in regs) into buf[kt&1]
        uint32_t* wd = gsm + (kt & 1) * 2 * HALF + lr * SROW + lc;
        *(uint4*)(wd)            = ra0;
        *(uint4*)(wd + 4)        = ra1;
        *(uint4*)(wd + HALF)     = rb0;
        *(uint4*)(wd + HALF + 4) = rb1;
        __syncthreads();

        // prefetch tile kt+1 (consumed at next iteration's store)
        if (kt + 1 < nt) {
            const float* An = Ap + (size_t)(kt + 1) * 16;
            const float* Bn = Bp + (size_t)(kt + 1) * 16;
            ra0 = *(const uint4*)(An);
            ra1 = *(const uint4*)(An + 4);
            rb0 = *(const uint4*)(Bn);
            rb1 = *(const uint4*)(Bn + 4);
        }

        // mma on buf[kt&1]
        const uint32_t* as = gsm + (kt & 1) * 2 * HALF;
        const uint32_t* bs = as + HALF;
#pragma unroll
        for (int kk = 0; kk < 16; kk += 8) {
            uint32_t af[2][4], bf[8][2];
#pragma unroll
            for (int mi = 0; mi < 2; mi++) {
                int r = wm * 32 + mi * 16 + g;
                af[mi][0] = as[r * SROW + kk + tg];
                af[mi][1] = as[(r + 8) * SROW + kk + tg];
                af[mi][2] = as[r * SROW + kk + tg + 4];
                af[mi][3] = as[(r + 8) * SROW + kk + tg + 4];
            }
#pragma unroll
            for (int ni = 0; ni < 8; ni++) {
                int n = wn * 64 + ni * 8 + g;
                bf[ni][0] = bs[n * SROW + kk + tg];
                bf[ni][1] = bs[n * SROW + kk + tg + 4];
            }
#pragma unroll
            for (int mi = 0; mi < 2; mi++)
#pragma unroll
                for (int ni = 0; ni < 8; ni++)
                    mma_tf32(acc[mi * 8 + ni],
                             af[mi][0], af[mi][1], af[mi][2], af[mi][3],
                             bf[ni][0], bf[ni][1]);
        }
        // no second barrier: buf[kt&1] is next written at iter kt+2, and the
        // barrier at the top of iter kt+1 orders those writes after these reads.
    }

#pragma unroll
    for (int mi = 0; mi < 2; mi++) {
        int row = bm + wm * 32 + mi * 16 + g;
#pragma unroll
        for (int ni = 0; ni < 8; ni++) {
            int col = bn + wn * 64 + ni * 8 + tg * 2;
            const float* a = acc[mi * 8 + ni];
            *(float2*)&C[(size_t)row * ldc + col]       = make_float2(a[0], a[1]);
            *(float2*)&C[(size_t)(row + 8) * ldc + col] = make_float2(a[2], a[3]);
        }
    }
}

// ---------------------------------------------------------------------------
// RoPE cos/sin table (double precision)
// ---------------------------------------------------------------------------
__global__ void rope_tab(const int* __restrict__ pos,
                         float* __restrict__ ct, float* __restrict__ st)
{
    int idx = blockIdx.x * blockDim.x + threadIdx.x;
    if (idx >= TT * 32) return;
    int t = idx >> 5, j = idx & 31;
    double ang = (double)pos[t] * pow(10000.0, -(double)j / 32.0);
    double s, c;
    sincos(ang, &s, &c);
    ct[idx] = (float)c;
    st[idx] = (float)s;
}

// ---------------------------------------------------------------------------
// RoPE + reshape; stores tf32-rounded so flash loads raw bits.
// ---------------------------------------------------------------------------
__global__ void rope_reshape(const float* __restrict__ qkv,
                             const float* __restrict__ ct, const float* __restrict__ st,
                             float* __restrict__ Qr, float* __restrict__ Kr)
{
    const int PPT = (HH + HKV) * 32;
    int idx = blockIdx.x * blockDim.x + threadIdx.x;
    if (idx >= BB * TT * PPT) return;
    int m = idx / PPT;
    int r = idx - m * PPT;
    int head = r >> 5, dp = r & 31;
    int b = m / TT, t = m - b * TT;

    const float* row = qkv + (size_t)m * NQKV;
    float x0, x1;
    float* dst;
    if (head < HH) {
        x0 = row[head * 64 + dp];
        x1 = row[head * 64 + dp + 32];
        dst = Qr + ((size_t)(b * HH + head) * TT + t) * 64;
    } else {
        int hk = head - HH;
        x0 = row[2048 + hk * 64 + dp];
        x1 = row[2048 + hk * 64 + dp + 32];
        dst = Kr + ((size_t)(b * HKV + hk) * TT + t) * 64;
    }
    int j = dp >> 1;
    float c1 = ct[t * 32 + j],      s1 = st[t * 32 + j];
    float c2 = ct[t * 32 + j + 16], s2 = st[t * 32 + j + 16];
    dst[dp]      = __uint_as_float(f2tf(x0 * c1 - x1 * s1));
    dst[dp + 32] = __uint_as_float(f2tf(x1 * c2 + x0 * s2));
}

// ---------------------------------------------------------------------------
// Tensor-core flash attention (tf32 mma, fp32 softmax in registers).
// Q/K/V pre-rounded to tf32 -> loads are raw bit copies.
// ---------------------------------------------------------------------------
#define FS 68
#define FLASH_SMEM (384 * FS * 4)

__global__ __launch_bounds__(256)
void flash_attn_tc(const float* __restrict__ Q, const float* __restrict__ K,
                   const float* __restrict__ Vg, float* __restrict__ Y)
{
    extern __shared__ uint32_t smu[];
    uint32_t* Qs = smu;                 // [128][FS]
    uint32_t* Ks = Qs + 128 * FS;       // [64][FS]
    uint32_t* Vs = Ks + 64 * FS;        // [64][FS]
    uint32_t* Ps = Vs + 64 * FS;        // [128][FS], per-warp-private rows

    const int tid = threadIdx.x;
    const int lane = tid & 31, w = tid >> 5;
    const int g = lane >> 2, tg = lane & 3;
    const int qt = (gridDim.x - 1) - blockIdx.x;   // heavy blocks first
    const int h = blockIdx.y, b = blockIdx.z, hk = h >> 2;
    const int qbase = qt * 128;
    const float scale = 0.125f;

    {
        int r = tid >> 1, c0 = (tid & 1) * 32;
        const uint4* src = (const uint4*)(Q + (((size_t)(b * HH + h) * TT) + qbase + r) * 64 + c0);
        uint4* dst = (uint4*)(Qs + r * FS + c0);
#pragma unroll
        for (int i = 0; i < 8; i++) dst[i] = src[i];
    }

    float Oc[8][4];
#pragma unroll
    for (int i = 0; i < 8; i++)
#pragma unroll
        for (int j = 0; j < 4; j++) Oc[i][j] = 0.f;

    float mrun0 = -1e30f, mrun1 = -1e30f, lrun0 = 0.f, lrun1 = 0.f;
    const int row0 = qbase + w * 16 + g;
    const int row1 = row0 + 8;
    const int slab = w * 16;

    const int nkv = 2 * qt + 2;
    for (int jt = 0; jt < nkv; jt++) {
        const int kbase = jt * 64;
        __syncthreads();
        {
            int r = tid >> 2, c0 = (tid & 3) * 16;
            const uint4* ks = (const uint4*)(K + (((size_t)(b * HKV + hk) * TT) + kbase + r) * 64 + c0);
            const uint4* vs = (const uint4*)(Vg + ((size_t)(b * TT + kbase + r)) * NQKV + hk * 64 + c0);
            uint4* kd = (uint4*)(Ks + r * FS + c0);
            uint4* vd = (uint4*)(Vs + r * FS + c0);
#pragma unroll
            for (int i = 0; i < 4; i++) {
                kd[i] = ks[i];
                vd[i] = vs[i];
            }
        }
        __syncthreads();

        float Sc[8][4];
#pragma unroll
        for (int i = 0; i < 8; i++)
#pragma unroll
            for (int j = 0; j < 4; j++) Sc[i][j] = 0.f;
#pragma unroll
        for (int kk = 0; kk < 64; kk += 8) {
            uint32_t a0 = Qs[(slab + g) * FS + kk + tg];
            uint32_t a1 = Qs[(slab + g + 8) * FS + kk + tg];
            uint32_t a2 = Qs[(slab + g) * FS + kk + tg + 4];
            uint32_t a3 = Qs[(slab + g + 8) * FS + kk + tg + 4];
#pragma unroll
            for (int ni = 0; ni < 8; ni++) {
                uint32_t b0 = Ks[(ni * 8 + g) * FS + kk + tg];
                uint32_t b1 = Ks[(ni * 8 + g) * FS + kk + tg + 4];
                mma_tf32(Sc[ni], a0, a1, a2, a3, b0, b1);
            }
        }

        const bool needmask = (kbase + 63) > (qbase + slab);
        float mx0 = -1e30f, mx1 = -1e30f;
#pragma unroll
        for (int ni = 0; ni < 8; ni++) {
            int c = kbase + ni * 8 + 2 * tg;
            float s0 = Sc[ni][0] * scale, s1 = Sc[ni][1] * scale;
            float s2 = Sc[ni][2] * scale, s3 = Sc[ni][3] * scale;
            if (needmask) {
                if (c     > row0) s0 = -1e30f;
                if (c + 1 > row0) s1 = -1e30f;
                if (c     > row1) s2 = -1e30f;
                if (c + 1 > row1) s3 = -1e30f;
            }
            Sc[ni][0] = s0; Sc[ni][1] = s1; Sc[ni][2] = s2; Sc[ni][3] = s3;
            mx0 = fmaxf(mx0, fmaxf(s0, s1));
            mx1 = fmaxf(mx1, fmaxf(s2, s3));
        }
        mx0 = fmaxf(mx0, __shfl_xor_sync(0xffffffffu, mx0, 1));
        mx0 = fmaxf(mx0, __shfl_xor_sync(0xffffffffu, mx0, 2));
        mx1 = fmaxf(mx1, __shfl_xor_sync(0xffffffffu, mx1, 1));
        mx1 = fmaxf(mx1, __shfl_xor_sync(0xffffffffu, mx1, 2));

        float nm0 = fmaxf(mrun0, mx0), nm1 = fmaxf(mrun1, mx1);
        float ps0 = 0.f, ps1 = 0.f;
#pragma unroll
        for (int ni = 0; ni < 8; ni++) {
            float p0 = __expf(Sc[ni][0] - nm0);
            float p1 = __expf(Sc[ni][1] - nm0);
            float p2 = __expf(Sc[ni][2] - nm1);
            float p3 = __expf(Sc[ni][3] - nm1);
            ps0 += p0 + p1; ps1 += p2 + p3;
            Ps[(slab + g) * FS + ni * 8 + 2 * tg]         = f2tf(p0);
            Ps[(slab + g) * FS + ni * 8 + 2 * tg + 1]     = f2tf(p1);
            Ps[(slab + g + 8) * FS + ni * 8 + 2 * tg]     = f2tf(p2);
            Ps[(slab + g + 8) * FS + ni * 8 + 2 * tg + 1] = f2tf(p3);
        }
        ps0 += __shfl_xor_sync(0xffffffffu, ps0, 1);
        ps0 += __shfl_xor_sync(0xffffffffu, ps0, 2);
        ps1 += __shfl_xor_sync(0xffffffffu, ps1, 1);
        ps1 += __shfl_xor_sync(0xffffffffu, ps1, 2);

        float rf0 = __expf(mrun0 - nm0), rf1 = __expf(mrun1 - nm1);
        lrun0 = lrun0 * rf0 + ps0;  lrun1 = lrun1 * rf1 + ps1;
        mrun0 = nm0;  mrun1 = nm1;
#pragma unroll
        for (int ni = 0; ni < 8; ni++) {
            Oc[ni][0] *= rf0; Oc[ni][1] *= rf0;
            Oc[ni][2] *= rf1; Oc[ni][3] *= rf1;
        }
        __syncwarp();

#pragma unroll
        for (int kk = 0; kk < 64; kk += 8) {
            uint32_t a0 = Ps[(slab + g) * FS + kk + tg];
            uint32_t a1 = Ps[(slab + g + 8) * FS + kk + tg];
            uint32_t a2 = Ps[(slab + g) * FS + kk + tg + 4];
            uint32_t a3 = Ps[(slab + g + 8) * FS + kk + tg + 4];
#pragma unroll
            for (int ni = 0; ni < 8; ni++) {
                uint32_t b0 = Vs[(kk + tg) * FS + ni * 8 + g];
                uint32_t b1 = Vs[(kk + tg + 4) * FS + ni * 8 + g];
                mma_tf32(Oc[ni], a0, a1, a2, a3, b0, b1);
            }
        }
    }

    // Normalize + tf32-round + write y (feeds proj GEMM raw)
    float inv0 = 1.0f / lrun0, inv1 = 1.0f / lrun1;
#pragma unroll
    for (int ni = 0; ni < 8; ni++) {
        int col = h * 64 + ni * 8 + 2 * tg;
        *(float2*)&Y[((size_t)(b * TT) + row0) * CC + col] =
            make_float2(__uint_as_float(f2tf(Oc[ni][0] * inv0)),
                        __uint_as_float(f2tf(Oc[ni][1] * inv0)));
        *(float2*)&Y[((size_t)(b * TT) + row1) * CC + col] =
            make_float2(__uint_as_float(f2tf(Oc[ni][2] * inv1)),
                        __uint_as_float(f2tf(Oc[ni][3] * inv1)));
    }
}

// ---------------------------------------------------------------------------
extern "C" void kernel_launch(void* const* d_in, const int* in_sizes, int n_in,
                              void* d_out, int out_size)
{
    const float* x  = (const float*)d_in[0];
    const float* Wq = (const float*)d_in[1];
    const float* Wk = (const float*)d_in[2];
    const float* Wv = (const float*)d_in[3];
    const float* Wc = (const float*)d_in[4];
    const int* pos  = (const int*)d_in[5];
    float* out = (float*)d_out;

    float *qkv, *q, *k, *y, *ct, *st, *xt, *wt, *wct;
    cudaGetSymbolAddress((void**)&qkv, g_qkv);
    cudaGetSymbolAddress((void**)&q,   g_q);
    cudaGetSymbolAddress((void**)&k,   g_k);
    cudaGetSymbolAddress((void**)&y,   g_y);
    cudaGetSymbolAddress((void**)&ct,  g_ct);
    cudaGetSymbolAddress((void**)&st,  g_st);
    cudaGetSymbolAddress((void**)&xt,  g_xt);
    cudaGetSymbolAddress((void**)&wt,  g_wt);
    cudaGetSymbolAddress((void**)&wct, g_wct);

    cudaFuncSetAttribute(gemm_tf32, cudaFuncAttributeMaxDynamicSharedMemorySize, GEMM_SMEM);
    cudaFuncSetAttribute(flash_attn_tc, cudaFuncAttributeMaxDynamicSharedMemorySize, FLASH_SMEM);

    // Pre-round operands to tf32
    round_tf<<<(MROWS * CC / 4) / 256, 256>>>(x, xt, MROWS * CC / 4);
    round_tf<<<(2048 * 2048 / 4) / 256, 256>>>(Wq, wt, 2048 * 2048 / 4);
    round_tf<<<(512 * 2048 / 4) / 256, 256>>>(Wk, wt + 2048 * 2048, 512 * 2048 / 4);
    round_tf<<<(512 * 2048 / 4) / 256, 256>>>(Wv, wt + 2560 * 2048, 512 * 2048 / 4);
    round_tf<<<(2048 * 2048 / 4) / 256, 256>>>(Wc, wct, 2048 * 2048 / 4);

    // QKV projection (M=4096, N=3072 packed)
    gemm_tf32<<<dim3(24, 32), 256, GEMM_SMEM>>>(xt, wt, qkv, NQKV);

    // RoPE
    rope_tab<<<(TT * 32 + 255) / 256, 256>>>(pos, ct, st);
    rope_reshape<<<(BB * TT * (HH + HKV) * 32 + 255) / 256, 256>>>(qkv, ct, st, q, k);
    round_v<<<(MROWS * 128) / 256, 256>>>(qkv);

    // Flash attention (tf32 mma.sync)
    flash_attn_tc<<<dim3(TT / 128, HH, BB), 256, FLASH_SMEM>>>(q, k, qkv + 2560, y);

    // Output projection
    gemm_tf32<<<dim3(16, 32), 256, GEMM_SMEM>>>(y, wct, out, CC);
}

// round 13
// speedup vs baseline: 1.4761x; 1.4042x over previous
#include <cuda_runtime.h>
#include <cuda_bf16.h>
#include <cstdint>
#include <math.h>

// Problem constants
#define BB 2
#define TT 2048
#define CC 2048
#define HH 32
#define HKV 8
#define DD 64
#define MROWS (BB*TT)          // 4096
#define NQKV 3072              // H*D + 2*HKV*D

// Scratch (device globals: allocation-free per harness rules)
__device__ float g_qkv[MROWS * NQKV];          // [m][3072]  q|k|v
__device__ float g_q[BB * HH * TT * DD];       // [b][h][t][d]  (RoPE'd, tf32-rounded)
__device__ float g_k[BB * HKV * TT * DD];      // [b][hk][t][d] (RoPE'd, tf32-rounded)
__device__ float g_y[MROWS * CC];              // attention out (tf32-rounded)
__device__ float g_ct[TT * 32];                // cos table
__device__ float g_st[TT * 32];                // sin table
// tf32-pre-rounded GEMM operands
__device__ float g_xt[MROWS * CC];             // x rounded
__device__ float g_wt[NQKV * CC];              // [Wq;Wk;Wv] rounded
__device__ float g_wct[CC * CC];               // Wc rounded

// ---------------------------------------------------------------------------
// helpers
// ---------------------------------------------------------------------------
__device__ __forceinline__ uint32_t f2tf(float f) {
    uint32_t r;
    asm("cvt.rna.tf32.f32 %0, %1;" : "=r"(r) : "f"(f));
    return r;
}

__device__ __forceinline__ void mma_tf32(float* c,
                                         uint32_t a0, uint32_t a1, uint32_t a2, uint32_t a3,
                                         uint32_t b0, uint32_t b1) {
    asm volatile(
        "mma.sync.aligned.m16n8k8.row.col.f32.tf32.tf32.f32 "
        "{%0,%1,%2,%3}, {%4,%5,%6,%7}, {%8,%9}, {%0,%1,%2,%3};"
        : "+f"(c[0]), "+f"(c[1]), "+f"(c[2]), "+f"(c[3])
        : "r"(a0), "r"(a1), "r"(a2), "r"(a3), "r"(b0), "r"(b1));
}

// ---------------------------------------------------------------------------
// elementwise tf32 rounding
// ---------------------------------------------------------------------------
__global__ void round_tf(const float* __restrict__ s, float* __restrict__ d, int n4)
{
    int i = blockIdx.x * blockDim.x + threadIdx.x;
    if (i >= n4) return;
    float4 v = ((const float4*)s)[i];
    v.x = __uint_as_float(f2tf(v.x));
    v.y = __uint_as_float(f2tf(v.y));
    v.z = __uint_as_float(f2tf(v.z));
    v.w = __uint_as_float(f2tf(v.w));
    ((float4*)d)[i] = v;
}

// round the V region of qkv (cols 2560..3071) in place
__global__ void round_v(float* __restrict__ qkv)
{
    int idx = blockIdx.x * blockDim.x + threadIdx.x;   // 4096*128
    int m = idx >> 7, c4 = idx & 127;
    float4* p = (float4*)(qkv + (size_t)m * NQKV + 2560) + c4;
    float4 v = *p;
    v.x = __uint_as_float(f2tf(v.x));
    v.y = __uint_as_float(f2tf(v.y));
    v.z = __uint_as_float(f2tf(v.z));
    v.w = __uint_as_float(f2tf(v.w));
    *p = v;
}

// ---------------------------------------------------------------------------
// tf32 tensor-core GEMM body — EXACT R6 structure (static 20 KB smem, single
// buffer, store -> sync -> prefetch -> mma -> sync). Operands pre-rounded to
// tf32, so the smem store path is raw uint4 (no cvt chain).
// C[m][n] = sum_k A[m][k]*B[n][k]; K = 2048.
// ---------------------------------------------------------------------------
#define SROW 20

__device__ __forceinline__ void gemm_body(const float* __restrict__ A,
                                          const float* __restrict__ B,
                                          float* __restrict__ C,
                                          int ldc, int bm, int bn)
{
    __shared__ uint32_t As[128 * SROW];
    __shared__ uint32_t Bs[128 * SROW];

    const int tid = threadIdx.x;
    const int lane = tid & 31, w = tid >> 5;
    const int wm = w >> 1, wn = w & 1;     // warp grid 4x2
    const int g = lane >> 2, tg = lane & 3;
    const int lr = tid >> 1;               // 0..127
    const int lc = (tid & 1) * 8;          // 0 or 8

    const float* Ap = A + (size_t)(bm + lr) * 2048 + lc;
    const float* Bp = B + (size_t)(bn + lr) * 2048 + lc;

    float acc[16][4];
#pragma unroll
    for (int i = 0; i < 16; i++)
#pragma unroll
        for (int j = 0; j < 4; j++) acc[i][j] = 0.f;

    const int nt = 128;   // K / 16

    uint4 ra0 = *(const uint4*)(Ap);
    uint4 ra1 = *(const uint4*)(Ap + 4);
    uint4 rb0 = *(const uint4*)(Bp);
    uint4 rb1 = *(const uint4*)(Bp + 4);

    uint32_t* ap = &As[lr * SROW + lc];
    uint32_t* bp = &Bs[lr * SROW + lc];

    for (int kt = 0; kt < nt; kt++) {
        // store current tile (raw bits; operands already tf32-rounded)
        *(uint4*)(ap)     = ra0;
        *(uint4*)(ap + 4) = ra1;
        *(uint4*)(bp)     = rb0;
        *(uint4*)(bp + 4) = rb1;
        __syncthreads();

        // prefetch next tile to registers (hidden under the mma block)
        if (kt + 1 < nt) {
            const float* An = Ap + (size_t)(kt + 1) * 16;
            const float* Bn = Bp + (size_t)(kt + 1) * 16;
            ra0 = *(const uint4*)(An);
            ra1 = *(const uint4*)(An + 4);
            rb0 = *(const uint4*)(Bn);
            rb1 = *(const uint4*)(Bn + 4);
        }

#pragma unroll
        for (int kk = 0; kk < 16; kk += 8) {
            uint32_t af[2][4], bf[8][2];
#pragma unroll
            for (int mi = 0; mi < 2; mi++) {
                int r = wm * 32 + mi * 16 + g;
                af[mi][0] = As[r * SROW + kk + tg];
                af[mi][1] = As[(r + 8) * SROW + kk + tg];
                af[mi][2] = As[r * SROW + kk + tg + 4];
                af[mi][3] = As[(r + 8) * SROW + kk + tg + 4];
            }
#pragma unroll
            for (int ni = 0; ni < 8; ni++) {
                int n = wn * 64 + ni * 8 + g;
                bf[ni][0] = Bs[n * SROW + kk + tg];
                bf[ni][1] = Bs[n * SROW + kk + tg + 4];
            }
#pragma unroll
            for (int mi = 0; mi < 2; mi++)
#pragma unroll
                for (int ni = 0; ni < 8; ni++)
                    mma_tf32(acc[mi * 8 + ni],
                             af[mi][0], af[mi][1], af[mi][2], af[mi][3],
                             bf[ni][0], bf[ni][1]);
        }
        __syncthreads();
    }

#pragma unroll
    for (int mi = 0; mi < 2; mi++) {
        int row = bm + wm * 32 + mi * 16 + g;
#pragma unroll
        for (int ni = 0; ni < 8; ni++) {
            int col = bn + wn * 64 + ni * 8 + tg * 2;
            const float* a = acc[mi * 8 + ni];
            *(float2*)&C[(size_t)row * ldc + col]       = make_float2(a[0], a[1]);
            *(float2*)&C[(size_t)(row + 8) * ldc + col] = make_float2(a[2], a[3]);
        }
    }
}

// Fused QKV projection: one launch covers the packed [Wq;Wk;Wv] (24 n-tiles).
__global__ __launch_bounds__(256)
void qkv_gemm(const float* __restrict__ xt, const float* __restrict__ wt,
              float* __restrict__ qkv)
{
    gemm_body(xt, wt, qkv, NQKV, blockIdx.y * 128, blockIdx.x * 128);
}

// Output projection: out = y @ Wc^T
__global__ __launch_bounds__(256)
void proj_gemm(const float* __restrict__ y, const float* __restrict__ wct,
               float* __restrict__ out)
{
    gemm_body(y, wct, out, CC, blockIdx.y * 128, blockIdx.x * 128);
}

// ---------------------------------------------------------------------------
// RoPE cos/sin table (double precision)
// ---------------------------------------------------------------------------
__global__ void rope_tab(const int* __restrict__ pos,
                         float* __restrict__ ct, float* __restrict__ st)
{
    int idx = blockIdx.x * blockDim.x + threadIdx.x;
    if (idx >= TT * 32) return;
    int t = idx >> 5, j = idx & 31;
    double ang = (double)pos[t] * pow(10000.0, -(double)j / 32.0);
    double s, c;
    sincos(ang, &s, &c);
    ct[idx] = (float)c;
    st[idx] = (float)s;
}

// ---------------------------------------------------------------------------
// RoPE + reshape; stores tf32-rounded so flash loads raw bits.
// ---------------------------------------------------------------------------
__global__ void rope_reshape(const float* __restrict__ qkv,
                             const float* __restrict__ ct, const float* __restrict__ st,
                             float* __restrict__ Qr, float* __restrict__ Kr)
{
    const int PPT = (HH + HKV) * 32;
    int idx = blockIdx.x * blockDim.x + threadIdx.x;
    if (idx >= BB * TT * PPT) return;
    int m = idx / PPT;
    int r = idx - m * PPT;
    int head = r >> 5, dp = r & 31;
    int b = m / TT, t = m - b * TT;

    const float* row = qkv + (size_t)m * NQKV;
    float x0, x1;
    float* dst;
    if (head < HH) {
        x0 = row[head * 64 + dp];
        x1 = row[head * 64 + dp + 32];
        dst = Qr + ((size_t)(b * HH + head) * TT + t) * 64;
    } else {
        int hk = head - HH;
        x0 = row[2048 + hk * 64 + dp];
        x1 = row[2048 + hk * 64 + dp + 32];
        dst = Kr + ((size_t)(b * HKV + hk) * TT + t) * 64;
    }
    int j = dp >> 1;
    float c1 = ct[t * 32 + j],      s1 = st[t * 32 + j];
    float c2 = ct[t * 32 + j + 16], s2 = st[t * 32 + j + 16];
    dst[dp]      = __uint_as_float(f2tf(x0 * c1 - x1 * s1));
    dst[dp + 32] = __uint_as_float(f2tf(x1 * c2 + x0 * s2));
}

// ---------------------------------------------------------------------------
// Tensor-core flash attention (tf32 mma, fp32 softmax in registers).
// Q/K/V pre-rounded to tf32 -> loads are raw bit copies.
// ---------------------------------------------------------------------------
#define FS 68
#define FLASH_SMEM (384 * FS * 4)

__global__ __launch_bounds__(256)
void flash_attn_tc(const float* __restrict__ Q, const float* __restrict__ K,
                   const float* __restrict__ Vg, float* __restrict__ Y)
{
    extern __shared__ uint32_t smu[];
    uint32_t* Qs = smu;                 // [128][FS]
    uint32_t* Ks = Qs + 128 * FS;       // [64][FS]
    uint32_t* Vs = Ks + 64 * FS;        // [64][FS]
    uint32_t* Ps = Vs + 64 * FS;        // [128][FS], per-warp-private rows

    const int tid = threadIdx.x;
    const int lane = tid & 31, w = tid >> 5;
    const int g = lane >> 2, tg = lane & 3;
    const int qt = (gridDim.x - 1) - blockIdx.x;   // heavy blocks first
    const int h = blockIdx.y, b = blockIdx.z, hk = h >> 2;
    const int qbase = qt * 128;
    const float scale = 0.125f;

    {
        int r = tid >> 1, c0 = (tid & 1) * 32;
        const uint4* src = (const uint4*)(Q + (((size_t)(b * HH + h) * TT) + qbase + r) * 64 + c0);
        uint4* dst = (uint4*)(Qs + r * FS + c0);
#pragma unroll
        for (int i = 0; i < 8; i++) dst[i] = src[i];
    }

    float Oc[8][4];
#pragma unroll
    for (int i = 0; i < 8; i++)
#pragma unroll
        for (int j = 0; j < 4; j++) Oc[i][j] = 0.f;

    float mrun0 = -1e30f, mrun1 = -1e30f, lrun0 = 0.f, lrun1 = 0.f;
    const int row0 = qbase + w * 16 + g;
    const int row1 = row0 + 8;
    const int slab = w * 16;

    const int nkv = 2 * qt + 2;
    for (int jt = 0; jt < nkv; jt++) {
        const int kbase = jt * 64;
        __syncthreads();
        {
            int r = tid >> 2, c0 = (tid & 3) * 16;
            const uint4* ks = (const uint4*)(K + (((size_t)(b * HKV + hk) * TT) + kbase + r) * 64 + c0);
            const uint4* vs = (const uint4*)(Vg + ((size_t)(b * TT + kbase + r)) * NQKV + hk * 64 + c0);
            uint4* kd = (uint4*)(Ks + r * FS + c0);
            uint4* vd = (uint4*)(Vs + r * FS + c0);
#pragma unroll
            for (int i = 0; i < 4; i++) {
                kd[i] = ks[i];
                vd[i] = vs[i];
            }
        }
        __syncthreads();

        float Sc[8][4];
#pragma unroll
        for (int i = 0; i < 8; i++)
#pragma unroll
            for (int j = 0; j < 4; j++) Sc[i][j] = 0.f;
#pragma unroll
        for (int kk = 0; kk < 64; kk += 8) {
            uint32_t a0 = Qs[(slab + g) * FS + kk + tg];
            uint32_t a1 = Qs[(slab + g + 8) * FS + kk + tg];
            uint32_t a2 = Qs[(slab + g) * FS + kk + tg + 4];
            uint32_t a3 = Qs[(slab + g + 8) * FS + kk + tg + 4];
#pragma unroll
            for (int ni = 0; ni < 8; ni++) {
                uint32_t b0 = Ks[(ni * 8 + g) * FS + kk + tg];
                uint32_t b1 = Ks[(ni * 8 + g) * FS + kk + tg + 4];
                mma_tf32(Sc[ni], a0, a1, a2, a3, b0, b1);
            }
        }

        const bool needmask = (kbase + 63) > (qbase + slab);
        float mx0 = -1e30f, mx1 = -1e30f;
#pragma unroll
        for (int ni = 0; ni < 8; ni++) {
            int c = kbase + ni * 8 + 2 * tg;
            float s0 = Sc[ni][0] * scale, s1 = Sc[ni][1] * scale;
            float s2 = Sc[ni][2] * scale, s3 = Sc[ni][3] * scale;
            if (needmask) {
                if (c     > row0) s0 = -1e30f;
                if (c + 1 > row0) s1 = -1e30f;
                if (c     > row1) s2 = -1e30f;
                if (c + 1 > row1) s3 = -1e30f;
            }
            Sc[ni][0] = s0; Sc[ni][1] = s1; Sc[ni][2] = s2; Sc[ni][3] = s3;
            mx0 = fmaxf(mx0, fmaxf(s0, s1));
            mx1 = fmaxf(mx1, fmaxf(s2, s3));
        }
        mx0 = fmaxf(mx0, __shfl_xor_sync(0xffffffffu, mx0, 1));
        mx0 = fmaxf(mx0, __shfl_xor_sync(0xffffffffu, mx0, 2));
        mx1 = fmaxf(mx1, __shfl_xor_sync(0xffffffffu, mx1, 1));
        mx1 = fmaxf(mx1, __shfl_xor_sync(0xffffffffu, mx1, 2));

        float nm0 = fmaxf(mrun0, mx0), nm1 = fmaxf(mrun1, mx1);
        float ps0 = 0.f, ps1 = 0.f;
#pragma unroll
        for (int ni = 0; ni < 8; ni++) {
            float p0 = __expf(Sc[ni][0] - nm0);
            float p1 = __expf(Sc[ni][1] - nm0);
            float p2 = __expf(Sc[ni][2] - nm1);
            float p3 = __expf(Sc[ni][3] - nm1);
            ps0 += p0 + p1; ps1 += p2 + p3;
            Ps[(slab + g) * FS + ni * 8 + 2 * tg]         = f2tf(p0);
            Ps[(slab + g) * FS + ni * 8 + 2 * tg + 1]     = f2tf(p1);
            Ps[(slab + g + 8) * FS + ni * 8 + 2 * tg]     = f2tf(p2);
            Ps[(slab + g + 8) * FS + ni * 8 + 2 * tg + 1] = f2tf(p3);
        }
        ps0 += __shfl_xor_sync(0xffffffffu, ps0, 1);
        ps0 += __shfl_xor_sync(0xffffffffu, ps0, 2);
        ps1 += __shfl_xor_sync(0xffffffffu, ps1, 1);
        ps1 += __shfl_xor_sync(0xffffffffu, ps1, 2);

        float rf0 = __expf(mrun0 - nm0), rf1 = __expf(mrun1 - nm1);
        lrun0 = lrun0 * rf0 + ps0;  lrun1 = lrun1 * rf1 + ps1;
        mrun0 = nm0;  mrun1 = nm1;
#pragma unroll
        for (int ni = 0; ni < 8; ni++) {
            Oc[ni][0] *= rf0; Oc[ni][1] *= rf0;
            Oc[ni][2] *= rf1; Oc[ni][3] *= rf1;
        }
        __syncwarp();

#pragma unroll
        for (int kk = 0; kk < 64; kk += 8) {
            uint32_t a0 = Ps[(slab + g) * FS + kk + tg];
            uint32_t a1 = Ps[(slab + g + 8) * FS + kk + tg];
            uint32_t a2 = Ps[(slab + g) * FS + kk + tg + 4];
            uint32_t a3 = Ps[(slab + g + 8) * FS + kk + tg + 4];
#pragma unroll
            for (int ni = 0; ni < 8; ni++) {
                uint32_t b0 = Vs[(kk + tg) * FS + ni * 8 + g];
                uint32_t b1 = Vs[(kk + tg + 4) * FS + ni * 8 + g];
                mma_tf32(Oc[ni], a0, a1, a2, a3, b0, b1);
            }
        }
    }

    // Normalize + tf32-round + write y (feeds proj GEMM raw)
    float inv0 = 1.0f / lrun0, inv1 = 1.0f / lrun1;
#pragma unroll
    for (int ni = 0; ni < 8; ni++) {
        int col = h * 64 + ni * 8 + 2 * tg;
        *(float2*)&Y[((size_t)(b * TT) + row0) * CC + col] =
            make_float2(__uint_as_float(f2tf(Oc[ni][0] * inv0)),
                        __uint_as_float(f2tf(Oc[ni][1] * inv0)));
        *(float2*)&Y[((size_t)(b * TT) + row1) * CC + col] =
            make_float2(__uint_as_float(f2tf(Oc[ni][2] * inv1)),
                        __uint_as_float(f2tf(Oc[ni][3] * inv1)));
    }
}

// ---------------------------------------------------------------------------
extern "C" void kernel_launch(void* const* d_in, const int* in_sizes, int n_in,
                              void* d_out, int out_size)
{
    const float* x  = (const float*)d_in[0];
    const float* Wq = (const float*)d_in[1];
    const float* Wk = (const float*)d_in[2];
    const float* Wv = (const float*)d_in[3];
    const float* Wc = (const float*)d_in[4];
    const int* pos  = (const int*)d_in[5];
    float* out = (float*)d_out;

    float *qkv, *q, *k, *y, *ct, *st, *xt, *wt, *wct;
    cudaGetSymbolAddress((void**)&qkv, g_qkv);
    cudaGetSymbolAddress((void**)&q,   g_q);
    cudaGetSymbolAddress((void**)&k,   g_k);
    cudaGetSymbolAddress((void**)&y,   g_y);
    cudaGetSymbolAddress((void**)&ct,  g_ct);
    cudaGetSymbolAddress((void**)&st,  g_st);
    cudaGetSymbolAddress((void**)&xt,  g_xt);
    cudaGetSymbolAddress((void**)&wt,  g_wt);
    cudaGetSymbolAddress((void**)&wct, g_wct);

    cudaFuncSetAttribute(flash_attn_tc, cudaFuncAttributeMaxDynamicSharedMemorySize, FLASH_SMEM);

    // Pre-round operands to tf32
    round_tf<<<(MROWS * CC / 4) / 256, 256>>>(x, xt, MROWS * CC / 4);
    round_tf<<<(2048 * 2048 / 4) / 256, 256>>>(Wq, wt, 2048 * 2048 / 4);
    round_tf<<<(512 * 2048 / 4) / 256, 256>>>(Wk, wt + 2048 * 2048, 512 * 2048 / 4);
    round_tf<<<(512 * 2048 / 4) / 256, 256>>>(Wv, wt + 2560 * 2048, 512 * 2048 / 4);
    round_tf<<<(2048 * 2048 / 4) / 256, 256>>>(Wc, wct, 2048 * 2048 / 4);

    // QKV projection (M=4096, N=3072 packed) — R6 structure, 20 KB smem
    qkv_gemm<<<dim3(24, 32), 256>>>(xt, wt, qkv);

    // RoPE
    rope_tab<<<(TT * 32 + 255) / 256, 256>>>(pos, ct, st);
    rope_reshape<<<(BB * TT * (HH + HKV) * 32 + 255) / 256, 256>>>(qkv, ct, st, q, k);
    round_v<<<(MROWS * 128) / 256, 256>>>(qkv);

    // Flash attention (tf32 mma.sync)
    flash_attn_tc<<<dim3(TT / 128, HH, BB), 256, FLASH_SMEM>>>(q, k, qkv + 2560, y);

    // Output projection
    proj_gemm<<<dim3(16, 32), 256>>>(y, wct, out);
}

// round 14
// speedup vs baseline: 1.5429x; 1.0452x over previous
#include <cuda_runtime.h>
#include <cuda_bf16.h>
#include <cstdint>
#include <math.h>

// Problem constants
#define BB 2
#define TT 2048
#define CC 2048
#define HH 32
#define HKV 8
#define DD 64
#define MROWS (BB*TT)          // 4096
#define NQKV 3072              // H*D + 2*HKV*D

// Scratch (device globals: allocation-free per harness rules)
__device__ float g_qkv[MROWS * NQKV];          // [m][3072]  q|k|v
__device__ float g_q[BB * HH * TT * DD];       // [b][h][t][d]  (RoPE'd, tf32-rounded)
__device__ float g_k[BB * HKV * TT * DD];      // [b][hk][t][d] (RoPE'd, tf32-rounded)
__device__ float g_y[MROWS * CC];              // attention out (tf32-rounded)
__device__ float g_ct[TT * 32];                // cos table
__device__ float g_st[TT * 32];                // sin table
// tf32-pre-rounded GEMM operands
__device__ float g_xt[MROWS * CC];             // x rounded
__device__ float g_wt[NQKV * CC];              // [Wq;Wk;Wv] rounded
__device__ float g_wct[CC * CC];               // Wc rounded

// ---------------------------------------------------------------------------
// helpers
// ---------------------------------------------------------------------------
__device__ __forceinline__ uint32_t f2tf(float f) {
    uint32_t r;
    asm("cvt.rna.tf32.f32 %0, %1;" : "=r"(r) : "f"(f));
    return r;
}

__device__ __forceinline__ void mma_tf32(float* c,
                                         uint32_t a0, uint32_t a1, uint32_t a2, uint32_t a3,
                                         uint32_t b0, uint32_t b1) {
    asm volatile(
        "mma.sync.aligned.m16n8k8.row.col.f32.tf32.tf32.f32 "
        "{%0,%1,%2,%3}, {%4,%5,%6,%7}, {%8,%9}, {%0,%1,%2,%3};"
        : "+f"(c[0]), "+f"(c[1]), "+f"(c[2]), "+f"(c[3])
        : "r"(a0), "r"(a1), "r"(a2), "r"(a3), "r"(b0), "r"(b1));
}

// ---------------------------------------------------------------------------
// elementwise tf32 rounding
// ---------------------------------------------------------------------------
__global__ void round_tf(const float* __restrict__ s, float* __restrict__ d, int n4)
{
    int i = blockIdx.x * blockDim.x + threadIdx.x;
    if (i >= n4) return;
    float4 v = ((const float4*)s)[i];
    v.x = __uint_as_float(f2tf(v.x));
    v.y = __uint_as_float(f2tf(v.y));
    v.z = __uint_as_float(f2tf(v.z));
    v.w = __uint_as_float(f2tf(v.w));
    ((float4*)d)[i] = v;
}

// round the V region of qkv (cols 2560..3071) in place
__global__ void round_v(float* __restrict__ qkv)
{
    int idx = blockIdx.x * blockDim.x + threadIdx.x;   // 4096*128
    int m = idx >> 7, c4 = idx & 127;
    float4* p = (float4*)(qkv + (size_t)m * NQKV + 2560) + c4;
    float4 v = *p;
    v.x = __uint_as_float(f2tf(v.x));
    v.y = __uint_as_float(f2tf(v.y));
    v.z = __uint_as_float(f2tf(v.z));
    v.w = __uint_as_float(f2tf(v.w));
    *p = v;
}

// ---------------------------------------------------------------------------
// tf32 tensor-core GEMM body — R6 structure (static 20 KB smem, single buffer,
// store -> sync -> prefetch -> mma -> sync). Operands pre-rounded to tf32.
// C[m][n] = sum_k A[m][k]*B[n][k]; K = 2048.
// ---------------------------------------------------------------------------
#define SROW 20

__device__ __forceinline__ void gemm_body(const float* __restrict__ A,
                                          const float* __restrict__ B,
                                          float* __restrict__ C,
                                          int ldc, int bm, int bn)
{
    __shared__ uint32_t As[128 * SROW];
    __shared__ uint32_t Bs[128 * SROW];

    const int tid = threadIdx.x;
    const int lane = tid & 31, w = tid >> 5;
    const int wm = w >> 1, wn = w & 1;     // warp grid 4x2
    const int g = lane >> 2, tg = lane & 3;
    const int lr = tid >> 1;               // 0..127
    const int lc = (tid & 1) * 8;          // 0 or 8

    const float* Ap = A + (size_t)(bm + lr) * 2048 + lc;
    const float* Bp = B + (size_t)(bn + lr) * 2048 + lc;

    float acc[16][4];
#pragma unroll
    for (int i = 0; i < 16; i++)
#pragma unroll
        for (int j = 0; j < 4; j++) acc[i][j] = 0.f;

    const int nt = 128;   // K / 16

    uint4 ra0 = *(const uint4*)(Ap);
    uint4 ra1 = *(const uint4*)(Ap + 4);
    uint4 rb0 = *(const uint4*)(Bp);
    uint4 rb1 = *(const uint4*)(Bp + 4);

    uint32_t* ap = &As[lr * SROW + lc];
    uint32_t* bp = &Bs[lr * SROW + lc];

    for (int kt = 0; kt < nt; kt++) {
        *(uint4*)(ap)     = ra0;
        *(uint4*)(ap + 4) = ra1;
        *(uint4*)(bp)     = rb0;
        *(uint4*)(bp + 4) = rb1;
        __syncthreads();

        if (kt + 1 < nt) {
            const float* An = Ap + (size_t)(kt + 1) * 16;
            const float* Bn = Bp + (size_t)(kt + 1) * 16;
            ra0 = *(const uint4*)(An);
            ra1 = *(const uint4*)(An + 4);
            rb0 = *(const uint4*)(Bn);
            rb1 = *(const uint4*)(Bn + 4);
        }

#pragma unroll
        for (int kk = 0; kk < 16; kk += 8) {
            uint32_t af[2][4], bf[8][2];
#pragma unroll
            for (int mi = 0; mi < 2; mi++) {
                int r = wm * 32 + mi * 16 + g;
                af[mi][0] = As[r * SROW + kk + tg];
                af[mi][1] = As[(r + 8) * SROW + kk + tg];
                af[mi][2] = As[r * SROW + kk + tg + 4];
                af[mi][3] = As[(r + 8) * SROW + kk + tg + 4];
            }
#pragma unroll
            for (int ni = 0; ni < 8; ni++) {
                int n = wn * 64 + ni * 8 + g;
                bf[ni][0] = Bs[n * SROW + kk + tg];
                bf[ni][1] = Bs[n * SROW + kk + tg + 4];
            }
#pragma unroll
            for (int mi = 0; mi < 2; mi++)
#pragma unroll
                for (int ni = 0; ni < 8; ni++)
                    mma_tf32(acc[mi * 8 + ni],
                             af[mi][0], af[mi][1], af[mi][2], af[mi][3],
                             bf[ni][0], bf[ni][1]);
        }
        __syncthreads();
    }

#pragma unroll
    for (int mi = 0; mi < 2; mi++) {
        int row = bm + wm * 32 + mi * 16 + g;
#pragma unroll
        for (int ni = 0; ni < 8; ni++) {
            int col = bn + wn * 64 + ni * 8 + tg * 2;
            const float* a = acc[mi * 8 + ni];
            *(float2*)&C[(size_t)row * ldc + col]       = make_float2(a[0], a[1]);
            *(float2*)&C[(size_t)(row + 8) * ldc + col] = make_float2(a[2], a[3]);
        }
    }
}

// Fused QKV projection over packed [Wq;Wk;Wv]
__global__ __launch_bounds__(256)
void qkv_gemm(const float* __restrict__ xt, const float* __restrict__ wt,
              float* __restrict__ qkv)
{
    gemm_body(xt, wt, qkv, NQKV, blockIdx.y * 128, blockIdx.x * 128);
}

// Output projection: out = y @ Wc^T
__global__ __launch_bounds__(256)
void proj_gemm(const float* __restrict__ y, const float* __restrict__ wct,
               float* __restrict__ out)
{
    gemm_body(y, wct, out, CC, blockIdx.y * 128, blockIdx.x * 128);
}

// ---------------------------------------------------------------------------
// RoPE cos/sin table (double precision)
// ---------------------------------------------------------------------------
__global__ void rope_tab(const int* __restrict__ pos,
                         float* __restrict__ ct, float* __restrict__ st)
{
    int idx = blockIdx.x * blockDim.x + threadIdx.x;
    if (idx >= TT * 32) return;
    int t = idx >> 5, j = idx & 31;
    double ang = (double)pos[t] * pow(10000.0, -(double)j / 32.0);
    double s, c;
    sincos(ang, &s, &c);
    ct[idx] = (float)c;
    st[idx] = (float)s;
}

// ---------------------------------------------------------------------------
// RoPE + reshape; stores tf32-rounded so flash loads raw bits.
// ---------------------------------------------------------------------------
__global__ void rope_reshape(const float* __restrict__ qkv,
                             const float* __restrict__ ct, const float* __restrict__ st,
                             float* __restrict__ Qr, float* __restrict__ Kr)
{
    const int PPT = (HH + HKV) * 32;
    int idx = blockIdx.x * blockDim.x + threadIdx.x;
    if (idx >= BB * TT * PPT) return;
    int m = idx / PPT;
    int r = idx - m * PPT;
    int head = r >> 5, dp = r & 31;
    int b = m / TT, t = m - b * TT;

    const float* row = qkv + (size_t)m * NQKV;
    float x0, x1;
    float* dst;
    if (head < HH) {
        x0 = row[head * 64 + dp];
        x1 = row[head * 64 + dp + 32];
        dst = Qr + ((size_t)(b * HH + head) * TT + t) * 64;
    } else {
        int hk = head - HH;
        x0 = row[2048 + hk * 64 + dp];
        x1 = row[2048 + hk * 64 + dp + 32];
        dst = Kr + ((size_t)(b * HKV + hk) * TT + t) * 64;
    }
    int j = dp >> 1;
    float c1 = ct[t * 32 + j],      s1 = st[t * 32 + j];
    float c2 = ct[t * 32 + j + 16], s2 = st[t * 32 + j + 16];
    dst[dp]      = __uint_as_float(f2tf(x0 * c1 - x1 * s1));
    dst[dp + 32] = __uint_as_float(f2tf(x1 * c2 + x0 * s2));
}

// ---------------------------------------------------------------------------
// Tensor-core flash attention (tf32 mma, fp32 softmax in registers).
// Bank-conflict-free layouts:
//   Qs/Ks/Ps row stride 68 (=4 mod 32): fragment loads hit 32 distinct banks.
//   Vs row stride 72 (=8 mod 32): transposed b-frag loads (tg*8+g) hit 32
//   distinct banks (stride 68 gave 2-way conflicts on 128 LDS/thread/tile).
//   P written as 64-bit pairs (adjacent cols) -> half the stores, no even-bank
//   conflict.
// ---------------------------------------------------------------------------
#define FS 68
#define VS 72
#define FLASH_SMEM ((128 * FS + 64 * FS + 64 * VS + 128 * FS) * 4)

__global__ __launch_bounds__(256)
void flash_attn_tc(const float* __restrict__ Q, const float* __restrict__ K,
                   const float* __restrict__ Vg, float* __restrict__ Y)
{
    extern __shared__ uint32_t smu[];
    uint32_t* Qs = smu;                 // [128][FS]
    uint32_t* Ks = Qs + 128 * FS;       // [64][FS]
    uint32_t* Vs = Ks + 64 * FS;        // [64][VS]
    uint32_t* Ps = Vs + 64 * VS;        // [128][FS], per-warp-private rows

    const int tid = threadIdx.x;
    const int lane = tid & 31, w = tid >> 5;
    const int g = lane >> 2, tg = lane & 3;
    const int qt = (gridDim.x - 1) - blockIdx.x;   // heavy blocks first
    const int h = blockIdx.y, b = blockIdx.z, hk = h >> 2;
    const int qbase = qt * 128;
    const float scale = 0.125f;

    {
        int r = tid >> 1, c0 = (tid & 1) * 32;
        const uint4* src = (const uint4*)(Q + (((size_t)(b * HH + h) * TT) + qbase + r) * 64 + c0);
        uint4* dst = (uint4*)(Qs + r * FS + c0);
#pragma unroll
        for (int i = 0; i < 8; i++) dst[i] = src[i];
    }

    float Oc[8][4];
#pragma unroll
    for (int i = 0; i < 8; i++)
#pragma unroll
        for (int j = 0; j < 4; j++) Oc[i][j] = 0.f;

    float mrun0 = -1e30f, mrun1 = -1e30f, lrun0 = 0.f, lrun1 = 0.f;
    const int row0 = qbase + w * 16 + g;
    const int row1 = row0 + 8;
    const int slab = w * 16;

    const int nkv = 2 * qt + 2;
    for (int jt = 0; jt < nkv; jt++) {
        const int kbase = jt * 64;
        __syncthreads();
        {
            int r = tid >> 2, c0 = (tid & 3) * 16;
            const uint4* ks = (const uint4*)(K + (((size_t)(b * HKV + hk) * TT) + kbase + r) * 64 + c0);
            const uint4* vs = (const uint4*)(Vg + ((size_t)(b * TT + kbase + r)) * NQKV + hk * 64 + c0);
            uint4* kd = (uint4*)(Ks + r * FS + c0);
            uint4* vd = (uint4*)(Vs + r * VS + c0);
#pragma unroll
            for (int i = 0; i < 4; i++) {
                kd[i] = ks[i];
                vd[i] = vs[i];
            }
        }
        __syncthreads();

        float Sc[8][4];
#pragma unroll
        for (int i = 0; i < 8; i++)
#pragma unroll
            for (int j = 0; j < 4; j++) Sc[i][j] = 0.f;
#pragma unroll
        for (int kk = 0; kk < 64; kk += 8) {
            uint32_t a0 = Qs[(slab + g) * FS + kk + tg];
            uint32_t a1 = Qs[(slab + g + 8) * FS + kk + tg];
            uint32_t a2 = Qs[(slab + g) * FS + kk + tg + 4];
            uint32_t a3 = Qs[(slab + g + 8) * FS + kk + tg + 4];
#pragma unroll
            for (int ni = 0; ni < 8; ni++) {
                uint32_t b0 = Ks[(ni * 8 + g) * FS + kk + tg];
                uint32_t b1 = Ks[(ni * 8 + g) * FS + kk + tg + 4];
                mma_tf32(Sc[ni], a0, a1, a2, a3, b0, b1);
            }
        }

        const bool needmask = (kbase + 63) > (qbase + slab);
        float mx0 = -1e30f, mx1 = -1e30f;
#pragma unroll
        for (int ni = 0; ni < 8; ni++) {
            int c = kbase + ni * 8 + 2 * tg;
            float s0 = Sc[ni][0] * scale, s1 = Sc[ni][1] * scale;
            float s2 = Sc[ni][2] * scale, s3 = Sc[ni][3] * scale;
            if (needmask) {
                if (c     > row0) s0 = -1e30f;
                if (c + 1 > row0) s1 = -1e30f;
                if (c     > row1) s2 = -1e30f;
                if (c + 1 > row1) s3 = -1e30f;
            }
            Sc[ni][0] = s0; Sc[ni][1] = s1; Sc[ni][2] = s2; Sc[ni][3] = s3;
            mx0 = fmaxf(mx0, fmaxf(s0, s1));
            mx1 = fmaxf(mx1, fmaxf(s2, s3));
        }
        mx0 = fmaxf(mx0, __shfl_xor_sync(0xffffffffu, mx0, 1));
        mx0 = fmaxf(mx0, __shfl_xor_sync(0xffffffffu, mx0, 2));
        mx1 = fmaxf(mx1, __shfl_xor_sync(0xffffffffu, mx1, 1));
        mx1 = fmaxf(mx1, __shfl_xor_sync(0xffffffffu, mx1, 2));

        float nm0 = fmaxf(mrun0, mx0), nm1 = fmaxf(mrun1, mx1);
        float ps0 = 0.f, ps1 = 0.f;
#pragma unroll
        for (int ni = 0; ni < 8; ni++) {
            float p0 = __expf(Sc[ni][0] - nm0);
            float p1 = __expf(Sc[ni][1] - nm0);
            float p2 = __expf(Sc[ni][2] - nm1);
            float p3 = __expf(Sc[ni][3] - nm1);
            ps0 += p0 + p1; ps1 += p2 + p3;
            uint2 w0; w0.x = f2tf(p0); w0.y = f2tf(p1);
            uint2 w1; w1.x = f2tf(p2); w1.y = f2tf(p3);
            *(uint2*)&Ps[(slab + g) * FS + ni * 8 + 2 * tg]     = w0;
            *(uint2*)&Ps[(slab + g + 8) * FS + ni * 8 + 2 * tg] = w1;
        }
        ps0 += __shfl_xor_sync(0xffffffffu, ps0, 1);
        ps0 += __shfl_xor_sync(0xffffffffu, ps0, 2);
        ps1 += __shfl_xor_sync(0xffffffffu, ps1, 1);
        ps1 += __shfl_xor_sync(0xffffffffu, ps1, 2);

        float rf0 = __expf(mrun0 - nm0), rf1 = __expf(mrun1 - nm1);
        lrun0 = lrun0 * rf0 + ps0;  lrun1 = lrun1 * rf1 + ps1;
        mrun0 = nm0;  mrun1 = nm1;
#pragma unroll
        for (int ni = 0; ni < 8; ni++) {
            Oc[ni][0] *= rf0; Oc[ni][1] *= rf0;
            Oc[ni][2] *= rf1; Oc[ni][3] *= rf1;
        }
        __syncwarp();

#pragma unroll
        for (int kk = 0; kk < 64; kk += 8) {
            uint32_t a0 = Ps[(slab + g) * FS + kk + tg];
            uint32_t a1 = Ps[(slab + g + 8) * FS + kk + tg];
            uint32_t a2 = Ps[(slab + g) * FS + kk + tg + 4];
            uint32_t a3 = Ps[(slab + g + 8) * FS + kk + tg + 4];
#pragma unroll
            for (int ni = 0; ni < 8; ni++) {
                uint32_t b0 = Vs[(kk + tg) * VS + ni * 8 + g];
                uint32_t b1 = Vs[(kk + tg + 4) * VS + ni * 8 + g];
                mma_tf32(Oc[ni], a0, a1, a2, a3, b0, b1);
            }
        }
    }

    // Normalize + tf32-round + write y (feeds proj GEMM raw)
    float inv0 = 1.0f / lrun0, inv1 = 1.0f / lrun1;
#pragma unroll
    for (int ni = 0; ni < 8; ni++) {
        int col = h * 64 + ni * 8 + 2 * tg;
        *(float2*)&Y[((size_t)(b * TT) + row0) * CC + col] =
            make_float2(__uint_as_float(f2tf(Oc[ni][0] * inv0)),
                        __uint_as_float(f2tf(Oc[ni][1] * inv0)));
        *(float2*)&Y[((size_t)(b * TT) + row1) * CC + col] =
            make_float2(__uint_as_float(f2tf(Oc[ni][2] * inv1)),
                        __uint_as_float(f2tf(Oc[ni][3] * inv1)));
    }
}

// ---------------------------------------------------------------------------
extern "C" void kernel_launch(void* const* d_in, const int* in_sizes, int n_in,
                              void* d_out, int out_size)
{
    const float* x  = (const float*)d_in[0];
    const float* Wq = (const float*)d_in[1];
    const float* Wk = (const float*)d_in[2];
    const float* Wv = (const float*)d_in[3];
    const float* Wc = (const float*)d_in[4];
    const int* pos  = (const int*)d_in[5];
    float* out = (float*)d_out;

    float *qkv, *q, *k, *y, *ct, *st, *xt, *wt, *wct;
    cudaGetSymbolAddress((void**)&qkv, g_qkv);
    cudaGetSymbolAddress((void**)&q,   g_q);
    cudaGetSymbolAddress((void**)&k,   g_k);
    cudaGetSymbolAddress((void**)&y,   g_y);
    cudaGetSymbolAddress((void**)&ct,  g_ct);
    cudaGetSymbolAddress((void**)&st,  g_st);
    cudaGetSymbolAddress((void**)&xt,  g_xt);
    cudaGetSymbolAddress((void**)&wt,  g_wt);
    cudaGetSymbolAddress((void**)&wct, g_wct);

    cudaFuncSetAttribute(flash_attn_tc, cudaFuncAttributeMaxDynamicSharedMemorySize, FLASH_SMEM);

    // Pre-round operands to tf32
    round_tf<<<(MROWS * CC / 4) / 256, 256>>>(x, xt, MROWS * CC / 4);
    round_tf<<<(2048 * 2048 / 4) / 256, 256>>>(Wq, wt, 2048 * 2048 / 4);
    round_tf<<<(512 * 2048 / 4) / 256, 256>>>(Wk, wt + 2048 * 2048, 512 * 2048 / 4);
    round_tf<<<(512 * 2048 / 4) / 256, 256>>>(Wv, wt + 2560 * 2048, 512 * 2048 / 4);
    round_tf<<<(2048 * 2048 / 4) / 256, 256>>>(Wc, wct, 2048 * 2048 / 4);

    // QKV projection (M=4096, N=3072 packed) — 20 KB smem GEMM
    qkv_gemm<<<dim3(24, 32), 256>>>(xt, wt, qkv);

    // RoPE
    rope_tab<<<(TT * 32 + 255) / 256, 256>>>(pos, ct, st);
    rope_reshape<<<(BB * TT * (HH + HKV) * 32 + 255) / 256, 256>>>(qkv, ct, st, q, k);
    round_v<<<(MROWS * 128) / 256, 256>>>(qkv);

    // Flash attention (tf32 mma.sync, conflict-free smem layouts)
    flash_attn_tc<<<dim3(TT / 128, HH, BB), 256, FLASH_SMEM>>>(q, k, qkv + 2560, y);

    // Output projection
    proj_gemm<<<dim3(16, 32), 256>>>(y, wct, out);
}

// round 15
// speedup vs baseline: 1.5721x; 1.0189x over previous
#include <cuda_runtime.h>
#include <cuda_bf16.h>
#include <cstdint>
#include <math.h>

// Problem constants
#define BB 2
#define TT 2048
#define CC 2048
#define HH 32
#define HKV 8
#define DD 64
#define MROWS (BB*TT)          // 4096
#define NQKV 3072              // H*D + 2*HKV*D

// Scratch (device globals: allocation-free per harness rules)
__device__ float g_qkv[MROWS * NQKV];          // [m][3072]  q|k|v
__device__ float g_q[BB * HH * TT * DD];       // [b][h][t][d]  (RoPE'd, tf32-rounded)
__device__ float g_k[BB * HKV * TT * DD];      // [b][hk][t][d] (RoPE'd, tf32-rounded)
__device__ float g_y[MROWS * CC];              // attention out (tf32-rounded)
__device__ float g_ct[TT * 32];                // cos table
__device__ float g_st[TT * 32];                // sin table
// tf32-pre-rounded GEMM operands
__device__ float g_xt[MROWS * CC];             // x rounded
__device__ float g_wt[NQKV * CC];              // [Wq;Wk;Wv] rounded
__device__ float g_wct[CC * CC];               // Wc rounded

// ---------------------------------------------------------------------------
// helpers
// ---------------------------------------------------------------------------
__device__ __forceinline__ uint32_t f2tf(float f) {
    uint32_t r;
    asm("cvt.rna.tf32.f32 %0, %1;" : "=r"(r) : "f"(f));
    return r;
}

__device__ __forceinline__ void mma_tf32(float* c,
                                         uint32_t a0, uint32_t a1, uint32_t a2, uint32_t a3,
                                         uint32_t b0, uint32_t b1) {
    asm volatile(
        "mma.sync.aligned.m16n8k8.row.col.f32.tf32.tf32.f32 "
        "{%0,%1,%2,%3}, {%4,%5,%6,%7}, {%8,%9}, {%0,%1,%2,%3};"
        : "+f"(c[0]), "+f"(c[1]), "+f"(c[2]), "+f"(c[3])
        : "r"(a0), "r"(a1), "r"(a2), "r"(a3), "r"(b0), "r"(b1));
}

__device__ __forceinline__ uint32_t smem_u32(const void* p) {
    uint32_t a;
    asm("{ .reg .u64 t; cvta.to.shared.u64 t, %1; cvt.u32.u64 %0, t; }" : "=r"(a) : "l"(p));
    return a;
}

__device__ __forceinline__ void cp16(uint32_t d, const void* s) {
    asm volatile("cp.async.cg.shared.global [%0], [%1], 16;" :: "r"(d), "l"(s) : "memory");
}
__device__ __forceinline__ void cp_commit() {
    asm volatile("cp.async.commit_group;" ::: "memory");
}
template<int N> __device__ __forceinline__ void cp_wait() {
    asm volatile("cp.async.wait_group %0;" :: "n"(N) : "memory");
}

// ---------------------------------------------------------------------------
// elementwise tf32 rounding
// ---------------------------------------------------------------------------
__global__ void round_tf(const float* __restrict__ s, float* __restrict__ d, int n4)
{
    int i = blockIdx.x * blockDim.x + threadIdx.x;
    if (i >= n4) return;
    float4 v = ((const float4*)s)[i];
    v.x = __uint_as_float(f2tf(v.x));
    v.y = __uint_as_float(f2tf(v.y));
    v.z = __uint_as_float(f2tf(v.z));
    v.w = __uint_as_float(f2tf(v.w));
    ((float4*)d)[i] = v;
}

// round the V region of qkv (cols 2560..3071) in place
__global__ void round_v(float* __restrict__ qkv)
{
    int idx = blockIdx.x * blockDim.x + threadIdx.x;   // 4096*128
    int m = idx >> 7, c4 = idx & 127;
    float4* p = (float4*)(qkv + (size_t)m * NQKV + 2560) + c4;
    float4 v = *p;
    v.x = __uint_as_float(f2tf(v.x));
    v.y = __uint_as_float(f2tf(v.y));
    v.z = __uint_as_float(f2tf(v.z));
    v.w = __uint_as_float(f2tf(v.w));
    *p = v;
}

// ---------------------------------------------------------------------------
// tf32 tensor-core GEMM body — R6 structure (static 20 KB smem, single buffer,
// store -> sync -> prefetch -> mma -> sync). Operands pre-rounded to tf32.
// C[m][n] = sum_k A[m][k]*B[n][k]; K = 2048.
// ---------------------------------------------------------------------------
#define SROW 20

__device__ __forceinline__ void gemm_body(const float* __restrict__ A,
                                          const float* __restrict__ B,
                                          float* __restrict__ C,
                                          int ldc, int bm, int bn)
{
    __shared__ uint32_t As[128 * SROW];
    __shared__ uint32_t Bs[128 * SROW];

    const int tid = threadIdx.x;
    const int lane = tid & 31, w = tid >> 5;
    const int wm = w >> 1, wn = w & 1;     // warp grid 4x2
    const int g = lane >> 2, tg = lane & 3;
    const int lr = tid >> 1;               // 0..127
    const int lc = (tid & 1) * 8;          // 0 or 8

    const float* Ap = A + (size_t)(bm + lr) * 2048 + lc;
    const float* Bp = B + (size_t)(bn + lr) * 2048 + lc;

    float acc[16][4];
#pragma unroll
    for (int i = 0; i < 16; i++)
#pragma unroll
        for (int j = 0; j < 4; j++) acc[i][j] = 0.f;

    const int nt = 128;   // K / 16

    uint4 ra0 = *(const uint4*)(Ap);
    uint4 ra1 = *(const uint4*)(Ap + 4);
    uint4 rb0 = *(const uint4*)(Bp);
    uint4 rb1 = *(const uint4*)(Bp + 4);

    uint32_t* ap = &As[lr * SROW + lc];
    uint32_t* bp = &Bs[lr * SROW + lc];

    for (int kt = 0; kt < nt; kt++) {
        *(uint4*)(ap)     = ra0;
        *(uint4*)(ap + 4) = ra1;
        *(uint4*)(bp)     = rb0;
        *(uint4*)(bp + 4) = rb1;
        __syncthreads();

        if (kt + 1 < nt) {
            const float* An = Ap + (size_t)(kt + 1) * 16;
            const float* Bn = Bp + (size_t)(kt + 1) * 16;
            ra0 = *(const uint4*)(An);
            ra1 = *(const uint4*)(An + 4);
            rb0 = *(const uint4*)(Bn);
            rb1 = *(const uint4*)(Bn + 4);
        }

#pragma unroll
        for (int kk = 0; kk < 16; kk += 8) {
            uint32_t af[2][4], bf[8][2];
#pragma unroll
            for (int mi = 0; mi < 2; mi++) {
                int r = wm * 32 + mi * 16 + g;
                af[mi][0] = As[r * SROW + kk + tg];
                af[mi][1] = As[(r + 8) * SROW + kk + tg];
                af[mi][2] = As[r * SROW + kk + tg + 4];
                af[mi][3] = As[(r + 8) * SROW + kk + tg + 4];
            }
#pragma unroll
            for (int ni = 0; ni < 8; ni++) {
                int n = wn * 64 + ni * 8 + g;
                bf[ni][0] = Bs[n * SROW + kk + tg];
                bf[ni][1] = Bs[n * SROW + kk + tg + 4];
            }
#pragma unroll
            for (int mi = 0; mi < 2; mi++)
#pragma unroll
                for (int ni = 0; ni < 8; ni++)
                    mma_tf32(acc[mi * 8 + ni],
                             af[mi][0], af[mi][1], af[mi][2], af[mi][3],
                             bf[ni][0], bf[ni][1]);
        }
        __syncthreads();
    }

#pragma unroll
    for (int mi = 0; mi < 2; mi++) {
        int row = bm + wm * 32 + mi * 16 + g;
#pragma unroll
        for (int ni = 0; ni < 8; ni++) {
            int col = bn + wn * 64 + ni * 8 + tg * 2;
            const float* a = acc[mi * 8 + ni];
            *(float2*)&C[(size_t)row * ldc + col]       = make_float2(a[0], a[1]);
            *(float2*)&C[(size_t)(row + 8) * ldc + col] = make_float2(a[2], a[3]);
        }
    }
}

// Fused QKV projection over packed [Wq;Wk;Wv]
__global__ __launch_bounds__(256)
void qkv_gemm(const float* __restrict__ xt, const float* __restrict__ wt,
              float* __restrict__ qkv)
{
    gemm_body(xt, wt, qkv, NQKV, blockIdx.y * 128, blockIdx.x * 128);
}

// Output projection: out = y @ Wc^T
__global__ __launch_bounds__(256)
void proj_gemm(const float* __restrict__ y, const float* __restrict__ wct,
               float* __restrict__ out)
{
    gemm_body(y, wct, out, CC, blockIdx.y * 128, blockIdx.x * 128);
}

// ---------------------------------------------------------------------------
// RoPE cos/sin table (double precision)
// ---------------------------------------------------------------------------
__global__ void rope_tab(const int* __restrict__ pos,
                         float* __restrict__ ct, float* __restrict__ st)
{
    int idx = blockIdx.x * blockDim.x + threadIdx.x;
    if (idx >= TT * 32) return;
    int t = idx >> 5, j = idx & 31;
    double ang = (double)pos[t] * pow(10000.0, -(double)j / 32.0);
    double s, c;
    sincos(ang, &s, &c);
    ct[idx] = (float)c;
    st[idx] = (float)s;
}

// ---------------------------------------------------------------------------
// RoPE + reshape; stores tf32-rounded so flash loads raw bits.
// ---------------------------------------------------------------------------
__global__ void rope_reshape(const float* __restrict__ qkv,
                             const float* __restrict__ ct, const float* __restrict__ st,
                             float* __restrict__ Qr, float* __restrict__ Kr)
{
    const int PPT = (HH + HKV) * 32;
    int idx = blockIdx.x * blockDim.x + threadIdx.x;
    if (idx >= BB * TT * PPT) return;
    int m = idx / PPT;
    int r = idx - m * PPT;
    int head = r >> 5, dp = r & 31;
    int b = m / TT, t = m - b * TT;

    const float* row = qkv + (size_t)m * NQKV;
    float x0, x1;
    float* dst;
    if (head < HH) {
        x0 = row[head * 64 + dp];
        x1 = row[head * 64 + dp + 32];
        dst = Qr + ((size_t)(b * HH + head) * TT + t) * 64;
    } else {
        int hk = head - HH;
        x0 = row[2048 + hk * 64 + dp];
        x1 = row[2048 + hk * 64 + dp + 32];
        dst = Kr + ((size_t)(b * HKV + hk) * TT + t) * 64;
    }
    int j = dp >> 1;
    float c1 = ct[t * 32 + j],      s1 = st[t * 32 + j];
    float c2 = ct[t * 32 + j + 16], s2 = st[t * 32 + j + 16];
    dst[dp]      = __uint_as_float(f2tf(x0 * c1 - x1 * s1));
    dst[dp + 32] = __uint_as_float(f2tf(x1 * c2 + x0 * s2));
}

// ---------------------------------------------------------------------------
// Tensor-core flash attention (tf32 mma, fp32 softmax in registers).
//  - Q fragments hoisted to registers (staged once through smem, region then
//    reused for Ps) -> 32 fewer LDS per thread per KV tile.
//  - K/V double-buffered in smem, filled by cp.async issued one full compute
//    iteration ahead -> L2 latency hidden behind the mma/softmax block.
//  - Conflict-free layouts from R14 (Ks/Ps stride 68, Vs stride 72, P stores
//    as 64-bit pairs).
// ---------------------------------------------------------------------------
#define FS 68
#define VS 72
// Ps (128xFS, doubles as Q staging) + 2x Ks (64xFS) + 2x Vs (64xVS)
#define FLASH_SMEM ((128 * FS + 2 * 64 * FS + 2 * 64 * VS) * 4)

__global__ __launch_bounds__(256, 2)
void flash_attn_tc(const float* __restrict__ Q, const float* __restrict__ K,
                   const float* __restrict__ Vg, float* __restrict__ Y)
{
    extern __shared__ uint32_t smu[];
    uint32_t* Ps = smu;                    // [128][FS]; Q staging in prologue
    uint32_t* Ks = smu + 128 * FS;         // [2][64][FS]
    uint32_t* Vs = Ks + 2 * 64 * FS;       // [2][64][VS]

    const int tid = threadIdx.x;
    const int lane = tid & 31, w = tid >> 5;
    const int g = lane >> 2, tg = lane & 3;
    const int qt = (gridDim.x - 1) - blockIdx.x;   // heavy blocks first
    const int h = blockIdx.y, b = blockIdx.z, hk = h >> 2;
    const int qbase = qt * 128;
    const float scale = 0.125f;
    const int nkv = 2 * qt + 2;

    // KV prefetch geometry (per thread: one row quarter, 4x16B for K and V)
    const int pr = tid >> 2, pc = (tid & 3) * 16;
    const float* Kg0 = K + (((size_t)(b * HKV + hk) * TT) + pr) * 64 + pc;
    const float* Vg0 = Vg + ((size_t)(b * TT + pr)) * NQKV + hk * 64 + pc;

    // issue tile 0 copy immediately (overlaps with Q staging below)
    {
        uint32_t kd = smem_u32(Ks + pr * FS + pc);
        uint32_t vd = smem_u32(Vs + pr * VS + pc);
#pragma unroll
        for (int i = 0; i < 4; i++) {
            cp16(kd + i * 16, Kg0 + i * 4);
            cp16(vd + i * 16, Vg0 + i * 4);
        }
        cp_commit();
    }

    // stage Q (coalesced) into the Ps region, then extract frags to registers
    {
        int r = tid >> 1, c0 = (tid & 1) * 32;
        const uint4* src = (const uint4*)(Q + (((size_t)(b * HH + h) * TT) + qbase + r) * 64 + c0);
        uint4* dst = (uint4*)(Ps + r * FS + c0);
#pragma unroll
        for (int i = 0; i < 8; i++) dst[i] = src[i];
    }
    __syncthreads();

    const int slab = w * 16;
    uint32_t qf[8][4];
#pragma unroll
    for (int k8 = 0; k8 < 8; k8++) {
        int kk = k8 * 8;
        qf[k8][0] = Ps[(slab + g) * FS + kk + tg];
        qf[k8][1] = Ps[(slab + g + 8) * FS + kk + tg];
        qf[k8][2] = Ps[(slab + g) * FS + kk + tg + 4];
        qf[k8][3] = Ps[(slab + g + 8) * FS + kk + tg + 4];
    }
    __syncthreads();   // Q extraction done before Ps is overwritten

    float Oc[8][4];
#pragma unroll
    for (int i = 0; i < 8; i++)
#pragma unroll
        for (int j = 0; j < 4; j++) Oc[i][j] = 0.f;

    float mrun0 = -1e30f, mrun1 = -1e30f, lrun0 = 0.f, lrun1 = 0.f;
    const int row0 = qbase + slab + g;
    const int row1 = row0 + 8;

    for (int jt = 0; jt < nkv; jt++) {
        cp_wait<0>();          // tile jt landed (issued one iteration ago)
        __syncthreads();       // visible to all warps; jt-1 readers done

        // prefetch tile jt+1 into the other buffer
        if (jt + 1 < nkv) {
            int kb = (jt + 1) * 64;
            int s = (jt + 1) & 1;
            uint32_t kd = smem_u32(Ks + s * 64 * FS + pr * FS + pc);
            uint32_t vd = smem_u32(Vs + s * 64 * VS + pr * VS + pc);
            const float* kg = Kg0 + (size_t)kb * 64;
            const float* vg = Vg0 + (size_t)kb * NQKV;
#pragma unroll
            for (int i = 0; i < 4; i++) {
                cp16(kd + i * 16, kg + i * 4);
                cp16(vd + i * 16, vg + i * 4);
            }
            cp_commit();
        }

        const int kbase = jt * 64;
        const uint32_t* Kb = Ks + (jt & 1) * 64 * FS;
        const uint32_t* Vb = Vs + (jt & 1) * 64 * VS;

        // S = Q K^T
        float Sc[8][4];
#pragma unroll
        for (int i = 0; i < 8; i++)
#pragma unroll
            for (int j = 0; j < 4; j++) Sc[i][j] = 0.f;
#pragma unroll
        for (int k8 = 0; k8 < 8; k8++) {
            int kk = k8 * 8;
#pragma unroll
            for (int ni = 0; ni < 8; ni++) {
                uint32_t b0 = Kb[(ni * 8 + g) * FS + kk + tg];
                uint32_t b1 = Kb[(ni * 8 + g) * FS + kk + tg + 4];
                mma_tf32(Sc[ni], qf[k8][0], qf[k8][1], qf[k8][2], qf[k8][3], b0, b1);
            }
        }

        const bool needmask = (kbase + 63) > (qbase + slab);
        float mx0 = -1e30f, mx1 = -1e30f;
#pragma unroll
        for (int ni = 0; ni < 8; ni++) {
            int c = kbase + ni * 8 + 2 * tg;
            float s0 = Sc[ni][0] * scale, s1 = Sc[ni][1] * scale;
            float s2 = Sc[ni][2] * scale, s3 = Sc[ni][3] * scale;
            if (needmask) {
                if (c     > row0) s0 = -1e30f;
                if (c + 1 > row0) s1 = -1e30f;
                if (c     > row1) s2 = -1e30f;
                if (c + 1 > row1) s3 = -1e30f;
            }
            Sc[ni][0] = s0; Sc[ni][1] = s1; Sc[ni][2] = s2; Sc[ni][3] = s3;
            mx0 = fmaxf(mx0, fmaxf(s0, s1));
            mx1 = fmaxf(mx1, fmaxf(s2, s3));
        }
        mx0 = fmaxf(mx0, __shfl_xor_sync(0xffffffffu, mx0, 1));
        mx0 = fmaxf(mx0, __shfl_xor_sync(0xffffffffu, mx0, 2));
        mx1 = fmaxf(mx1, __shfl_xor_sync(0xffffffffu, mx1, 1));
        mx1 = fmaxf(mx1, __shfl_xor_sync(0xffffffffu, mx1, 2));

        float nm0 = fmaxf(mrun0, mx0), nm1 = fmaxf(mrun1, mx1);
        float ps0 = 0.f, ps1 = 0.f;
#pragma unroll
        for (int ni = 0; ni < 8; ni++) {
            float p0 = __expf(Sc[ni][0] - nm0);
            float p1 = __expf(Sc[ni][1] - nm0);
            float p2 = __expf(Sc[ni][2] - nm1);
            float p3 = __expf(Sc[ni][3] - nm1);
            ps0 += p0 + p1; ps1 += p2 + p3;
            uint2 w0; w0.x = f2tf(p0); w0.y = f2tf(p1);
            uint2 w1; w1.x = f2tf(p2); w1.y = f2tf(p3);
            *(uint2*)&Ps[(slab + g) * FS + ni * 8 + 2 * tg]     = w0;
            *(uint2*)&Ps[(slab + g + 8) * FS + ni * 8 + 2 * tg] = w1;
        }
        ps0 += __shfl_xor_sync(0xffffffffu, ps0, 1);
        ps0 += __shfl_xor_sync(0xffffffffu, ps0, 2);
        ps1 += __shfl_xor_sync(0xffffffffu, ps1, 1);
        ps1 += __shfl_xor_sync(0xffffffffu, ps1, 2);

        float rf0 = __expf(mrun0 - nm0), rf1 = __expf(mrun1 - nm1);
        lrun0 = lrun0 * rf0 + ps0;  lrun1 = lrun1 * rf1 + ps1;
        mrun0 = nm0;  mrun1 = nm1;
#pragma unroll
        for (int ni = 0; ni < 8; ni++) {
            Oc[ni][0] *= rf0; Oc[ni][1] *= rf0;
            Oc[ni][2] *= rf1; Oc[ni][3] *= rf1;
        }
        __syncwarp();   // Ps rows are warp-private

        // O += P V
#pragma unroll
        for (int kk = 0; kk < 64; kk += 8) {
            uint32_t a0 = Ps[(slab + g) * FS + kk + tg];
            uint32_t a1 = Ps[(slab + g + 8) * FS + kk + tg];
            uint32_t a2 = Ps[(slab + g) * FS + kk + tg + 4];
            uint32_t a3 = Ps[(slab + g + 8) * FS + kk + tg + 4];
#pragma unroll
            for (int ni = 0; ni < 8; ni++) {
                uint32_t b0 = Vb[(kk + tg) * VS + ni * 8 + g];
                uint32_t b1 = Vb[(kk + tg + 4) * VS + ni * 8 + g];
                mma_tf32(Oc[ni], a0, a1, a2, a3, b0, b1);
            }
        }
    }

    // Normalize + tf32-round + write y (feeds proj GEMM raw)
    float inv0 = 1.0f / lrun0, inv1 = 1.0f / lrun1;
#pragma unroll
    for (int ni = 0; ni < 8; ni++) {
        int col = h * 64 + ni * 8 + 2 * tg;
        *(float2*)&Y[((size_t)(b * TT) + row0) * CC + col] =
            make_float2(__uint_as_float(f2tf(Oc[ni][0] * inv0)),
                        __uint_as_float(f2tf(Oc[ni][1] * inv0)));
        *(float2*)&Y[((size_t)(b * TT) + row1) * CC + col] =
            make_float2(__uint_as_float(f2tf(Oc[ni][2] * inv1)),
                        __uint_as_float(f2tf(Oc[ni][3] * inv1)));
    }
}

// ---------------------------------------------------------------------------
extern "C" void kernel_launch(void* const* d_in, const int* in_sizes, int n_in,
                              void* d_out, int out_size)
{
    const float* x  = (const float*)d_in[0];
    const float* Wq = (const float*)d_in[1];
    const float* Wk = (const float*)d_in[2];
    const float* Wv = (const float*)d_in[3];
    const float* Wc = (const float*)d_in[4];
    const int* pos  = (const int*)d_in[5];
    float* out = (float*)d_out;

    float *qkv, *q, *k, *y, *ct, *st, *xt, *wt, *wct;
    cudaGetSymbolAddress((void**)&qkv, g_qkv);
    cudaGetSymbolAddress((void**)&q,   g_q);
    cudaGetSymbolAddress((void**)&k,   g_k);
    cudaGetSymbolAddress((void**)&y,   g_y);
    cudaGetSymbolAddress((void**)&ct,  g_ct);
    cudaGetSymbolAddress((void**)&st,  g_st);
    cudaGetSymbolAddress((void**)&xt,  g_xt);
    cudaGetSymbolAddress((void**)&wt,  g_wt);
    cudaGetSymbolAddress((void**)&wct, g_wct);

    cudaFuncSetAttribute(flash_attn_tc, cudaFuncAttributeMaxDynamicSharedMemorySize, FLASH_SMEM);

    // Pre-round operands to tf32
    round_tf<<<(MROWS * CC / 4) / 256, 256>>>(x, xt, MROWS * CC / 4);
    round_tf<<<(2048 * 2048 / 4) / 256, 256>>>(Wq, wt, 2048 * 2048 / 4);
    round_tf<<<(512 * 2048 / 4) / 256, 256>>>(Wk, wt + 2048 * 2048, 512 * 2048 / 4);
    round_tf<<<(512 * 2048 / 4) / 256, 256>>>(Wv, wt + 2560 * 2048, 512 * 2048 / 4);
    round_tf<<<(2048 * 2048 / 4) / 256, 256>>>(Wc, wct, 2048 * 2048 / 4);

    // QKV projection (M=4096, N=3072 packed) — 20 KB smem GEMM
    qkv_gemm<<<dim3(24, 32), 256>>>(xt, wt, qkv);

    // RoPE
    rope_tab<<<(TT * 32 + 255) / 256, 256>>>(pos, ct, st);
    rope_reshape<<<(BB * TT * (HH + HKV) * 32 + 255) / 256, 256>>>(qkv, ct, st, q, k);
    round_v<<<(MROWS * 128) / 256, 256>>>(qkv);

    // Flash attention (tf32 mma.sync, Q in regs, cp.async double-buffered KV)
    flash_attn_tc<<<dim3(TT / 128, HH, BB), 256, FLASH_SMEM>>>(q, k, qkv + 2560, y);

    // Output projection
    proj_gemm<<<dim3(16, 32), 256>>>(y, wct, out);
}